// round 1
// baseline (speedup 1.0000x reference)
#include <cuda_runtime.h>
#include <math.h>

#define HN   4
#define DIN  257      // external feature dim (K of hyp GEMM; logical output dim)
#define DS   256      // space dim
#define DST  260      // internal padded row stride: [0..255]=space, [256]=time
#define MRF  64       // random-feature dim
#define NMAX 20000

// ---------------- scratch (device globals; no allocation) ----------------
__device__ float g_val_u [(size_t)HN * NMAX * DST];
__device__ float g_val_i [(size_t)HN * NMAX * DST];
__device__ float g_tmp   [(size_t)HN * NMAX * DST];   // hyp temp, later z_u
__device__ float g_z_i   [(size_t)HN * NMAX * DST];
__device__ float g_phi_uq[(size_t)HN * NMAX * MRF];
__device__ float g_phi_ik[(size_t)HN * NMAX * MRF];
__device__ float g_phi_iq[(size_t)HN * NMAX * MRF];
__device__ float g_phi_uk[(size_t)HN * NMAX * MRF];
__device__ float g_last_u[HN * MRF * DIN];
__device__ float g_last_i[HN * MRF * DIN];

__device__ __forceinline__ float* bufp(int s) {
    switch (s) {
        case 0: return g_val_u;  case 1: return g_val_i;
        case 2: return g_tmp;    case 3: return g_z_i;
        case 4: return g_phi_uq; case 5: return g_phi_ik;
        case 6: return g_phi_iq; case 7: return g_phi_uk;
        case 8: return g_last_u; default: return g_last_i;
    }
}

__device__ __forceinline__ float wsum(float v) {
#pragma unroll
    for (int m = 16; m >= 1; m >>= 1) v += __shfl_xor_sync(0xffffffffu, v, m);
    return v;
}

// ---------------- zero the `last` accumulators ----------------
__global__ void zero_last_kernel() {
    int idx = blockIdx.x * blockDim.x + threadIdx.x;
    if (idx < HN * MRF * DIN) { g_last_u[idx] = 0.f; g_last_i[idx] = 0.f; }
}

// ---------------- hyp_linear: out[h,n,:] = [space(256), time] ----------------
// GEMM x[N,257] @ W[h][257,256] + b[h]; time = sqrt(1 + sum(space^2)).
// Tile: 64 rows x 256 cols, K=257, double-buffered smem.
__global__ __launch_bounds__(256) void hyp_kernel(const float* __restrict__ x,
    const float* __restrict__ W, const float* __restrict__ bias, int out_sel, int N)
{
    float* out = bufp(out_sel);
    const int h  = blockIdx.y;
    const int r0 = blockIdx.x * 64;
    const int tid = threadIdx.x;
    const int tx = tid & 15, ty = tid >> 4;

    __shared__ __align__(16) float As[2][8][68];
    __shared__ __align__(16) float Bs[2][8][256];

    float acc[4][16];
#pragma unroll
    for (int r = 0; r < 4; r++)
#pragma unroll
        for (int c = 0; c < 16; c++) acc[r][c] = 0.f;

    const float* Wh = W + (size_t)h * DIN * DS;

    float  ra[2];
    float4 rb[2];

    // prologue: chunk 0
    {
#pragma unroll
        for (int j = 0; j < 2; j++) {
            int f = tid + j * 256;
            int kk = f & 7, row = f >> 3;
            int n = r0 + row;
            As[0][kk][row] = (n < N) ? x[(size_t)n * DIN + kk] : 0.f;
        }
#pragma unroll
        for (int j = 0; j < 2; j++) {
            int f4 = tid + j * 256;
            int kk = f4 >> 6, c4 = f4 & 63;
            float4 v = *(const float4*)(Wh + (size_t)kk * DS + c4 * 4);
            *(float4*)&Bs[0][kk][c4 * 4] = v;
        }
    }
    __syncthreads();

    const int NCH = (DIN + 7) / 8;  // 33
    for (int c = 0; c < NCH; c++) {
        int cur = c & 1;
        if (c + 1 < NCH) {
            int kc = c + 1;
#pragma unroll
            for (int j = 0; j < 2; j++) {
                int f = tid + j * 256;
                int kk = f & 7, row = f >> 3;
                int k = kc * 8 + kk, n = r0 + row;
                ra[j] = (k < DIN && n < N) ? x[(size_t)n * DIN + k] : 0.f;
            }
#pragma unroll
            for (int j = 0; j < 2; j++) {
                int f4 = tid + j * 256;
                int kk = f4 >> 6, c4 = f4 & 63;
                int k = kc * 8 + kk;
                rb[j] = (k < DIN) ? *(const float4*)(Wh + (size_t)k * DS + c4 * 4)
                                  : make_float4(0.f, 0.f, 0.f, 0.f);
            }
        }
#pragma unroll
        for (int kk = 0; kk < 8; kk++) {
            float4 a4 = *(const float4*)&As[cur][kk][ty * 4];
            float4 b4[4];
#pragma unroll
            for (int q = 0; q < 4; q++) b4[q] = *(const float4*)&Bs[cur][kk][tx * 4 + 64 * q];
            float av[4] = {a4.x, a4.y, a4.z, a4.w};
#pragma unroll
            for (int r = 0; r < 4; r++) {
#pragma unroll
                for (int q = 0; q < 4; q++) {
                    acc[r][q*4+0] += av[r] * b4[q].x;
                    acc[r][q*4+1] += av[r] * b4[q].y;
                    acc[r][q*4+2] += av[r] * b4[q].z;
                    acc[r][q*4+3] += av[r] * b4[q].w;
                }
            }
        }
        if (c + 1 < NCH) {
            __syncthreads();
            int nxt = 1 - cur;
#pragma unroll
            for (int j = 0; j < 2; j++) {
                int f = tid + j * 256;
                As[nxt][f & 7][f >> 3] = ra[j];
            }
#pragma unroll
            for (int j = 0; j < 2; j++) {
                int f4 = tid + j * 256;
                *(float4*)&Bs[nxt][f4 >> 6][(f4 & 63) * 4] = rb[j];
            }
            __syncthreads();
        }
    }

    // bias
    const float* bh = bias + h * DS;
#pragma unroll
    for (int q = 0; q < 4; q++) {
        float4 bv4 = *(const float4*)(bh + tx * 4 + 64 * q);
#pragma unroll
        for (int r = 0; r < 4; r++) {
            acc[r][q*4+0] += bv4.x;
            acc[r][q*4+1] += bv4.y;
            acc[r][q*4+2] += bv4.z;
            acc[r][q*4+3] += bv4.w;
        }
    }

    // sum of squares -> time, store
#pragma unroll
    for (int r = 0; r < 4; r++) {
        float s = 0.f;
#pragma unroll
        for (int c = 0; c < 16; c++) s += acc[r][c] * acc[r][c];
#pragma unroll
        for (int m = 1; m < 16; m <<= 1) s += __shfl_xor_sync(0xffffffffu, s, m);
        int n = r0 + ty * 4 + r;
        if (n < N) {
            float* ob = out + ((size_t)h * N + n) * DST;
#pragma unroll
            for (int q = 0; q < 4; q++) {
                float4 v = make_float4(acc[r][q*4+0], acc[r][q*4+1],
                                       acc[r][q*4+2], acc[r][q*4+3]);
                *(float4*)(ob + tx * 4 + 64 * q) = v;
            }
            if (tx == 0) ob[DS] = sqrtf(1.f + s);
        }
    }
}

// ---------------- phi = exp(space @ proj * sqrt(2)) * front ----------------
// front = exp(1 - t^2) * (1/sqrt(256)) + 1e-8
__global__ __launch_bounds__(256) void phi_kernel(int in_sel, const float* __restrict__ proj,
                                                  int out_sel, int N)
{
    const float* hyp = bufp(in_sel);
    float* phi = bufp(out_sel);
    const int h  = blockIdx.y;
    const int r0 = blockIdx.x * 128;
    const int tid = threadIdx.x;
    const int tx = tid & 15, ty = tid >> 4;

    __shared__ __align__(16) float As[2][16][132];
    __shared__ __align__(16) float Bs[2][16][64];

    float acc[8][4];
#pragma unroll
    for (int i = 0; i < 8; i++)
#pragma unroll
        for (int j = 0; j < 4; j++) acc[i][j] = 0.f;

    float  ra[8];
    float4 rb;

    // prologue: chunk 0
    {
#pragma unroll
        for (int j = 0; j < 8; j++) {
            int f = tid + j * 256;
            int kk = f & 15, row = f >> 4;
            int n = r0 + row;
            As[0][kk][row] = (n < N) ? hyp[((size_t)h * N + n) * DST + kk] : 0.f;
        }
        int kk = tid >> 4, c4 = tid & 15;
        *(float4*)&Bs[0][kk][c4 * 4] = *(const float4*)(proj + (size_t)kk * MRF + c4 * 4);
    }
    __syncthreads();

    const int NCH = DS / 16;  // 16
    for (int c = 0; c < NCH; c++) {
        int cur = c & 1;
        if (c + 1 < NCH) {
            int k0 = (c + 1) * 16;
#pragma unroll
            for (int j = 0; j < 8; j++) {
                int f = tid + j * 256;
                int kk = f & 15, row = f >> 4;
                int n = r0 + row;
                ra[j] = (n < N) ? hyp[((size_t)h * N + n) * DST + k0 + kk] : 0.f;
            }
            int kk = tid >> 4, c4 = tid & 15;
            rb = *(const float4*)(proj + (size_t)(k0 + kk) * MRF + c4 * 4);
        }
#pragma unroll
        for (int kk = 0; kk < 16; kk++) {
            float4 a0 = *(const float4*)&As[cur][kk][ty * 8];
            float4 a1 = *(const float4*)&As[cur][kk][ty * 8 + 4];
            float4 b  = *(const float4*)&Bs[cur][kk][tx * 4];
            float av[8] = {a0.x, a0.y, a0.z, a0.w, a1.x, a1.y, a1.z, a1.w};
#pragma unroll
            for (int i = 0; i < 8; i++) {
                acc[i][0] += av[i] * b.x;
                acc[i][1] += av[i] * b.y;
                acc[i][2] += av[i] * b.z;
                acc[i][3] += av[i] * b.w;
            }
        }
        if (c + 1 < NCH) {
            __syncthreads();
            int nxt = 1 - cur;
#pragma unroll
            for (int j = 0; j < 8; j++) {
                int f = tid + j * 256;
                As[nxt][f & 15][f >> 4] = ra[j];
            }
            int kk = tid >> 4, c4 = tid & 15;
            *(float4*)&Bs[nxt][kk][c4 * 4] = rb;
            __syncthreads();
        }
    }

    const float SQT = 1.41421356237309515f;  // 1/sqrt(tau), tau=0.5
#pragma unroll
    for (int i = 0; i < 8; i++) {
        int n = r0 + ty * 8 + i;
        if (n < N) {
            float t = hyp[((size_t)h * N + n) * DST + DS];
            float front = __expf(1.f - t * t) * 0.0625f + 1e-8f;
            float4 o;
            o.x = __expf(acc[i][0] * SQT) * front;
            o.y = __expf(acc[i][1] * SQT) * front;
            o.z = __expf(acc[i][2] * SQT) * front;
            o.w = __expf(acc[i][3] * SQT) * front;
            *(float4*)(phi + ((size_t)h * N + n) * MRF + tx * 4) = o;
        }
    }
}

// ---------------- last[h,m,d] = sum_n phi[h,n,m] * val[h,n,d] ----------------
// split-K over n with atomicAdd epilogue; d indexed in internal layout (256=time)
__global__ __launch_bounds__(256) void last_kernel(int phi_sel, int val_sel, int out_sel,
                                                   int N, int chunkRows)
{
    const float* ph  = bufp(phi_sel);
    const float* val = bufp(val_sel);
    float* lb = bufp(out_sel);
    const int d0 = blockIdx.x * 64;
    const int h  = blockIdx.y;
    const int n0 = blockIdx.z * chunkRows;
    const int tid = threadIdx.x;
    const int tx = tid & 15, ty = tid >> 4;
    const int nEnd = min(n0 + chunkRows, N);

    __shared__ __align__(16) float Ps[2][16][68];
    __shared__ __align__(16) float Vs[2][16][68];

    float acc[4][4];
#pragma unroll
    for (int i = 0; i < 4; i++)
#pragma unroll
        for (int j = 0; j < 4; j++) acc[i][j] = 0.f;

    const int kk = tid >> 4;   // row within 16-row chunk
    const int q4 = tid & 15;

    float4 rp;
    float  rv[4];

    // prologue
    {
        int n = n0 + kk;
        rp = (n < nEnd) ? *(const float4*)(ph + ((size_t)h * N + n) * MRF + q4 * 4)
                        : make_float4(0.f, 0.f, 0.f, 0.f);
        *(float4*)&Ps[0][kk][q4 * 4] = rp;
#pragma unroll
        for (int jj = 0; jj < 4; jj++) {
            int d = d0 + q4 * 4 + jj;
            Vs[0][kk][q4 * 4 + jj] = (n < nEnd && d < DIN)
                ? val[((size_t)h * N + n) * DST + d] : 0.f;
        }
    }
    __syncthreads();

    const int steps = (chunkRows + 15) / 16;
    for (int s = 0; s < steps; s++) {
        int cur = s & 1;
        if (s + 1 < steps) {
            int n = n0 + (s + 1) * 16 + kk;
            rp = (n < nEnd) ? *(const float4*)(ph + ((size_t)h * N + n) * MRF + q4 * 4)
                            : make_float4(0.f, 0.f, 0.f, 0.f);
#pragma unroll
            for (int jj = 0; jj < 4; jj++) {
                int d = d0 + q4 * 4 + jj;
                rv[jj] = (n < nEnd && d < DIN) ? val[((size_t)h * N + n) * DST + d] : 0.f;
            }
        }
#pragma unroll
        for (int k = 0; k < 16; k++) {
            float4 p = *(const float4*)&Ps[cur][k][ty * 4];
            float4 v = *(const float4*)&Vs[cur][k][tx * 4];
            float pv[4] = {p.x, p.y, p.z, p.w};
            float vv[4] = {v.x, v.y, v.z, v.w};
#pragma unroll
            for (int i = 0; i < 4; i++)
#pragma unroll
                for (int j = 0; j < 4; j++) acc[i][j] += pv[i] * vv[j];
        }
        if (s + 1 < steps) {
            __syncthreads();
            int nxt = 1 - cur;
            *(float4*)&Ps[nxt][kk][q4 * 4] = rp;
#pragma unroll
            for (int jj = 0; jj < 4; jj++) Vs[nxt][kk][q4 * 4 + jj] = rv[jj];
            __syncthreads();
        }
    }

#pragma unroll
    for (int i = 0; i < 4; i++)
#pragma unroll
        for (int j = 0; j < 4; j++) {
            int d = d0 + tx * 4 + j;
            if (d < DIN)
                atomicAdd(&lb[((size_t)h * MRF + ty * 4 + i) * DIN + d], acc[i][j]);
        }
}

// ---------------- z[h,n,:] = phi_q[h,n,:] @ last[h] ----------------
__global__ __launch_bounds__(256) void z_kernel(int phi_sel, int last_sel, int out_sel, int N)
{
    extern __shared__ __align__(16) float sh[];  // 64 x 260
    const float* phiq = bufp(phi_sel);
    const float* lb   = bufp(last_sel);
    float* z = bufp(out_sel);
    const int h = blockIdx.y;
    const int tid = threadIdx.x;

    for (int idx = tid; idx < MRF * DIN; idx += 256) {
        int m = idx / DIN;
        int d = idx - m * DIN;
        sh[m * 260 + d] = lb[(size_t)h * MRF * DIN + idx];
    }
    __syncthreads();

    int n = blockIdx.x * 256 + tid;
    if (n >= N) return;

    float q[64];
    const float* qp = phiq + ((size_t)h * N + n) * MRF;
#pragma unroll
    for (int m4 = 0; m4 < 16; m4++) {
        float4 v = *(const float4*)(qp + m4 * 4);
        q[m4 * 4 + 0] = v.x; q[m4 * 4 + 1] = v.y;
        q[m4 * 4 + 2] = v.z; q[m4 * 4 + 3] = v.w;
    }

    float* zr = z + ((size_t)h * N + n) * DST;
    for (int d4 = 0; d4 < 64; d4++) {
        float ax = 0.f, ay = 0.f, az = 0.f, aw = 0.f;
#pragma unroll
        for (int m = 0; m < 64; m++) {
            float4 L = *(const float4*)&sh[m * 260 + d4 * 4];
            ax += q[m] * L.x; ay += q[m] * L.y;
            az += q[m] * L.z; aw += q[m] * L.w;
        }
        float4 o = make_float4(ax, ay, az, aw);
        *(float4*)(zr + d4 * 4) = o;
    }
    float at = 0.f;
#pragma unroll
    for (int m = 0; m < 64; m++) at += q[m] * sh[m * 260 + 256];
    zr[256] = at;
}

// ---------------- finalize: normalize z, mobius add, head mean, hyper agg ----------------
// internal d': 0..255=space, 256=time; output index: time->0, space s->1+s
__global__ __launch_bounds__(256) void final_kernel(int val_sel, int z_sel,
                                                    float* __restrict__ out, int N)
{
    const float* val = bufp(val_sel);
    const float* zb  = bufp(z_sel);
    const int warp = threadIdx.x >> 5;
    const int lane = threadIdx.x & 31;
    const int n = blockIdx.x * 8 + warp;
    if (n >= N) return;

    float mean[9];
#pragma unroll
    for (int jj = 0; jj < 9; jj++) mean[jj] = 0.f;

    for (int h = 0; h < HN; h++) {
        const float* zr = zb  + ((size_t)h * N + n) * DST;
        const float* ar = val + ((size_t)h * N + n) * DST;
        float zv[9], av[9];
        float mq = 0.f;
#pragma unroll
        for (int jj = 0; jj < 9; jj++) {
            int d = lane + jj * 32;
            bool ok = d < DIN;
            float zz = ok ? zr[d] : 0.f;
            float aa = ok ? ar[d] : 0.f;
            zv[jj] = zz; av[jj] = aa;
            mq += zz * zz * ((d == DS) ? -1.f : 1.f);
        }
        mq = wsum(mq);
        float coeff = rsqrtf(fabsf(mq + 1e-7f));
        float ab = 0.f, a2 = 0.f, b2 = 0.f;
#pragma unroll
        for (int jj = 0; jj < 9; jj++) {
            float b = zv[jj] * coeff;
            zv[jj] = b;
            ab += av[jj] * b;
            a2 += av[jj] * av[jj];
            b2 += b * b;
        }
        ab = wsum(ab); a2 = wsum(a2); b2 = wsum(b2);
        float t1  = 1.f + 2.f * ab + b2;
        float t2  = 1.f - a2;
        float inv = 1.f / (1.f + 2.f * ab + a2 * b2 + 1e-7f);
#pragma unroll
        for (int jj = 0; jj < 9; jj++)
            mean[jj] += 0.25f * (t1 * av[jj] + t2 * zv[jj]) * inv;
    }

    float mq = 0.f;
#pragma unroll
    for (int jj = 0; jj < 9; jj++) {
        int d = lane + jj * 32;
        if (d < DIN) mq += mean[jj] * mean[jj] * ((d == DS) ? -1.f : 1.f);
    }
    mq = wsum(mq);
    float cf = rsqrtf(fabsf(mq) + 1e-7f);
#pragma unroll
    for (int jj = 0; jj < 9; jj++) {
        int d = lane + jj * 32;
        if (d < DIN) {
            int pos = (d == DS) ? 0 : (d + 1);   // time first, then space
            out[(size_t)n * DIN + pos] = mean[jj] * cf;
        }
    }
}

// ---------------- launch ----------------
extern "C" void kernel_launch(void* const* d_in, const int* in_sizes, int n_in,
                              void* d_out, int out_size)
{
    const float* u    = (const float*)d_in[0];
    const float* iT   = (const float*)d_in[1];
    const float* Wk   = (const float*)d_in[2];
    const float* bk   = (const float*)d_in[3];
    const float* Wq   = (const float*)d_in[4];
    const float* bq   = (const float*)d_in[5];
    const float* Wv   = (const float*)d_in[6];
    const float* bv   = (const float*)d_in[7];
    const float* proj = (const float*)d_in[8];
    float* out = (float*)d_out;
    const int N = in_sizes[0] / DIN;   // 20000

    cudaFuncSetAttribute(z_kernel, cudaFuncAttributeMaxDynamicSharedMemorySize,
                         MRF * 260 * (int)sizeof(float));

    dim3 bh(256);
    dim3 gh((N + 63) / 64, HN);
    dim3 gp((N + 127) / 128, HN);
    const int splits = 25;
    int chunkRows = (N + splits - 1) / splits;
    chunkRows = ((chunkRows + 15) / 16) * 16;
    dim3 gl(5, HN, splits);
    dim3 gz((N + 255) / 256, HN);
    dim3 gf((N + 7) / 8);
    const int zsm = MRF * 260 * (int)sizeof(float);

    zero_last_kernel<<<(HN * MRF * DIN + 255) / 256, 256>>>();

    hyp_kernel<<<gh, bh>>>(u,  Wv, bv, 0, N);          // val_u
    hyp_kernel<<<gh, bh>>>(iT, Wv, bv, 1, N);          // val_i
    hyp_kernel<<<gh, bh>>>(u,  Wq, bq, 2, N);          // tmp = u_query
    phi_kernel<<<gp, bh>>>(2, proj, 4, N);             // phi_uq
    hyp_kernel<<<gh, bh>>>(iT, Wk, bk, 2, N);          // tmp = i_key
    phi_kernel<<<gp, bh>>>(2, proj, 5, N);             // phi_ik
    hyp_kernel<<<gh, bh>>>(iT, Wq, bq, 2, N);          // tmp = i_query
    phi_kernel<<<gp, bh>>>(2, proj, 6, N);             // phi_iq
    hyp_kernel<<<gh, bh>>>(u,  Wk, bk, 2, N);          // tmp = u_key
    phi_kernel<<<gp, bh>>>(2, proj, 7, N);             // phi_uk

    last_kernel<<<gl, bh>>>(5, 1, 8, N, chunkRows);    // last_u = phi_ik^T @ val_i
    last_kernel<<<gl, bh>>>(7, 0, 9, N, chunkRows);    // last_i = phi_uk^T @ val_u

    z_kernel<<<gz, bh, zsm>>>(4, 8, 2, N);             // z_u -> tmp
    z_kernel<<<gz, bh, zsm>>>(6, 9, 3, N);             // z_i

    final_kernel<<<gf, bh>>>(0, 2, out, N);                      // u aggregate
    final_kernel<<<gf, bh>>>(1, 3, out + (size_t)N * DIN, N);    // i aggregate
}

// round 8
// speedup vs baseline: 1.4862x; 1.4862x over previous
#include <cuda_runtime.h>
#include <cuda_bf16.h>
#include <cstdint>
#include <math.h>

#define HN   4
#define DIN  257
#define DS   256
#define DST  260      // internal padded row: [0..255]=space, [256]=time
#define MRF  64
#define NMAX 20000
#define KP   288      // K padded for MMA (257 -> 288 zeros), 9 stages of 32
#define NSTG 9

// ---------------- scratch ----------------
__device__ float g_val_u [(size_t)HN * NMAX * DST];
__device__ float g_val_i [(size_t)HN * NMAX * DST];
__device__ float g_tmp   [(size_t)HN * NMAX * DST];
__device__ float g_z_i   [(size_t)HN * NMAX * DST];
__device__ float g_phi_uq[(size_t)HN * NMAX * MRF];
__device__ float g_phi_ik[(size_t)HN * NMAX * MRF];
__device__ float g_phi_iq[(size_t)HN * NMAX * MRF];
__device__ float g_phi_uk[(size_t)HN * NMAX * MRF];
__device__ float g_last_u[HN * MRF * DIN];
__device__ float g_last_i[HN * MRF * DIN];

// bf16 split buffers
__device__ __nv_bfloat16 g_xh_u[(size_t)NMAX * KP];
__device__ __nv_bfloat16 g_xl_u[(size_t)NMAX * KP];
__device__ __nv_bfloat16 g_xh_i[(size_t)NMAX * KP];
__device__ __nv_bfloat16 g_xl_i[(size_t)NMAX * KP];
__device__ __nv_bfloat16 g_wh[3][(size_t)HN * 256 * KP];   // [matrix][h][ncol][k]
__device__ __nv_bfloat16 g_wl[3][(size_t)HN * 256 * KP];

__device__ __forceinline__ float* bufp(int s) {
    switch (s) {
        case 0: return g_val_u;  case 1: return g_val_i;
        case 2: return g_tmp;    case 3: return g_z_i;
        case 4: return g_phi_uq; case 5: return g_phi_ik;
        case 6: return g_phi_iq; case 7: return g_phi_uk;
        case 8: return g_last_u; default: return g_last_i;
    }
}
__device__ __forceinline__ __nv_bfloat16* xhp(int s) { return s ? g_xh_i : g_xh_u; }
__device__ __forceinline__ __nv_bfloat16* xlp(int s) { return s ? g_xl_i : g_xl_u; }

__device__ __forceinline__ float wsum(float v) {
#pragma unroll
    for (int m = 16; m >= 1; m >>= 1) v += __shfl_xor_sync(0xffffffffu, v, m);
    return v;
}

__device__ __forceinline__ uint32_t smem_u32(const void* p) {
    uint32_t a;
    asm("{ .reg .u64 t; cvta.to.shared.u64 t, %1; cvt.u32.u64 %0, t; }" : "=r"(a) : "l"(p));
    return a;
}
__device__ __forceinline__ void cp16(uint32_t sa, const void* g) {
    asm volatile("cp.async.cg.shared.global [%0], [%1], 16;" :: "r"(sa), "l"(g));
}

#define LDSM_X4(r, addr)                                                           \
    asm volatile("ldmatrix.sync.aligned.m8n8.x4.shared.b16 {%0,%1,%2,%3}, [%4];"   \
        : "=r"((r)[0]), "=r"((r)[1]), "=r"((r)[2]), "=r"((r)[3]) : "r"(addr))
#define LDSM_X2(r, addr)                                                           \
    asm volatile("ldmatrix.sync.aligned.m8n8.x2.shared.b16 {%0,%1}, [%2];"         \
        : "=r"((r)[0]), "=r"((r)[1]) : "r"(addr))
#define MMA16816(d, a, b)                                                          \
    asm volatile("mma.sync.aligned.m16n8k16.row.col.f32.bf16.bf16.f32 "            \
        "{%0,%1,%2,%3},{%4,%5,%6,%7},{%8,%9},{%0,%1,%2,%3};"                       \
        : "+f"((d)[0]), "+f"((d)[1]), "+f"((d)[2]), "+f"((d)[3])                   \
        : "r"((a)[0]), "r"((a)[1]), "r"((a)[2]), "r"((a)[3]),                      \
          "r"((b)[0]), "r"((b)[1]))

// smem layout for hyp_mma: 2 stages of (Ah 4096 | Al 4096 | Bh 16384 | Bl 16384)
#define STG_BYTES 40960
#define OFF_AL 4096
#define OFF_BH 8192
#define OFF_BL 24576
#define SM_BIAS_OFF (2 * STG_BYTES)              // 81920, 256 floats
#define SM_SS_OFF   (SM_BIAS_OFF + 1024)         // 82944, 64 floats
#define SM_HYP_TOTAL (SM_SS_OFF + 256)           // 83200

// ---------------- converts ----------------
__global__ void convert_x_kernel(const float* __restrict__ x, int xsel, int N) {
    __nv_bfloat16* xh = xhp(xsel);
    __nv_bfloat16* xl = xlp(xsel);
    int idx = blockIdx.x * blockDim.x + threadIdx.x;
    if (idx >= N * KP) return;
    int n = idx / KP, k = idx - n * KP;
    float v = (k < DIN) ? x[(size_t)n * DIN + k] : 0.f;
    __nv_bfloat16 h = __float2bfloat16(v);
    __nv_bfloat16 l = __float2bfloat16(v - __bfloat162float(h));
    xh[idx] = h; xl[idx] = l;
}

// W[h, k, j] (k = DIN rows, j = DS cols) -> wh/wl[m][h, j, k] K-major, padded
__global__ void convert_w_kernel(const float* __restrict__ W, int m) {
    __nv_bfloat16* wh = g_wh[m];
    __nv_bfloat16* wl = g_wl[m];
    int idx = blockIdx.x * blockDim.x + threadIdx.x;
    if (idx >= HN * 256 * KP) return;
    int h = idx / (256 * KP);
    int r = idx - h * 256 * KP;
    int j = r / KP, k = r - j * KP;
    float v = (k < DIN) ? W[((size_t)h * DIN + k) * DS + j] : 0.f;
    __nv_bfloat16 hi = __float2bfloat16(v);
    __nv_bfloat16 lo = __float2bfloat16(v - __bfloat162float(hi));
    wh[idx] = hi; wl[idx] = lo;
}

__global__ void zero_last_kernel() {
    int idx = blockIdx.x * blockDim.x + threadIdx.x;
    if (idx < HN * MRF * DIN) { g_last_u[idx] = 0.f; g_last_i[idx] = 0.f; }
}

// ---------------- hyp_linear via mma.sync (split-bf16 3-term) ----------------
// CTA: 64 rows x 256 cols, K=288 in 9 stages of 32, double buffered.
// out[h,n,0..255] = x @ W[h] + b[h];  out[h,n,256] = sqrt(1 + sum(space^2))
__global__ __launch_bounds__(256, 2)
void hyp_mma_kernel(int xsel, int wmat, const float* __restrict__ bias,
                    int out_sel, int N)
{
    extern __shared__ char smem[];
    const int tid = threadIdx.x, wid = tid >> 5, lane = tid & 31;
    const int h = blockIdx.y, r0 = blockIdx.x * 64;
    float* out = bufp(out_sel);
    const __nv_bfloat16* xh = xhp(xsel);
    const __nv_bfloat16* xl = xlp(xsel);
    const __nv_bfloat16* wh = g_wh[wmat] + (size_t)h * 256 * KP;
    const __nv_bfloat16* wl = g_wl[wmat] + (size_t)h * 256 * KP;

    const uint32_t sb = smem_u32(smem);
    float* bias_s = (float*)(smem + SM_BIAS_OFF);
    float* ssbuf  = (float*)(smem + SM_SS_OFF);
    if (tid < 64) ssbuf[tid] = 0.f;
    bias_s[tid] = bias[h * DS + tid];

    auto load_stage = [&](int s) {
        const int k0 = s * 32;
        const uint32_t base = sb + (s & 1) * STG_BYTES;
        {   // A: 64 rows x 4 chunks of 8 bf16
            int row = tid >> 2, c = tid & 3;
            int n = min(r0 + row, N - 1);
            uint32_t dst = base + row * 64 + ((c ^ (row & 3)) << 4);
            cp16(dst,          xh + (size_t)n * KP + k0 + c * 8);
            cp16(dst + OFF_AL, xl + (size_t)n * KP + k0 + c * 8);
        }
#pragma unroll
        for (int i = 0; i < 4; i++) {   // B: 256 rows x 4 chunks
            int u = tid + i * 256;
            int row = u >> 2, c = u & 3;
            uint32_t dst = base + OFF_BH + row * 64 + ((c ^ (row & 3)) << 4);
            cp16(dst,                   wh + (size_t)row * KP + k0 + c * 8);
            cp16(dst + (OFF_BL-OFF_BH), wl + (size_t)row * KP + k0 + c * 8);
        }
        asm volatile("cp.async.commit_group;" ::: "memory");
    };

    float acc[16][4];
#pragma unroll
    for (int i = 0; i < 16; i++)
#pragma unroll
        for (int j = 0; j < 4; j++) acc[i][j] = 0.f;

    const int wm = wid >> 2, wn = wid & 3;   // warp tile: rows wm*32, cols wn*64

    load_stage(0);
    load_stage(1);

    for (int s = 0; s < NSTG; s++) {
        if (s + 1 < NSTG) asm volatile("cp.async.wait_group 1;" ::: "memory");
        else              asm volatile("cp.async.wait_group 0;" ::: "memory");
        __syncthreads();
        const uint32_t base = sb + (s & 1) * STG_BYTES;
#pragma unroll
        for (int kh = 0; kh < 2; kh++) {
            uint32_t ah[2][4], al[2][4];
#pragma unroll
            for (int mt = 0; mt < 2; mt++) {
                int r = wm * 32 + mt * 16 + (lane & 15);
                int ch = kh * 2 + ((lane >> 4) & 1);
                uint32_t ad = base + r * 64 + ((ch ^ (r & 3)) << 4);
                LDSM_X4(ah[mt], ad);
                LDSM_X4(al[mt], ad + OFF_AL);
            }
#pragma unroll
            for (int bt = 0; bt < 8; bt++) {
                int rr = wn * 64 + bt * 8 + (lane & 7);
                int ch = kh * 2 + ((lane >> 3) & 1);
                uint32_t bd = base + OFF_BH + rr * 64 + ((ch ^ (rr & 3)) << 4);
                uint32_t bh_[2], bl_[2];
                LDSM_X2(bh_, bd);
                LDSM_X2(bl_, bd + (OFF_BL - OFF_BH));
#pragma unroll
                for (int mt = 0; mt < 2; mt++) {
                    MMA16816(acc[mt*8+bt], ah[mt], bh_);
                    MMA16816(acc[mt*8+bt], ah[mt], bl_);
                    MMA16816(acc[mt*8+bt], al[mt], bh_);
                }
            }
        }
        __syncthreads();
        if (s + 2 < NSTG) load_stage(s + 2);
    }

    // ---- epilogue: bias, stores, row sum-of-squares, time ----
#pragma unroll
    for (int mt = 0; mt < 2; mt++) {
        float sslo = 0.f, sshi = 0.f;
        int rL = wm * 32 + mt * 16 + (lane >> 2);
        int n0 = r0 + rL, n1 = n0 + 8;
#pragma unroll
        for (int bt = 0; bt < 8; bt++) {
            float* d = acc[mt*8+bt];
            int cL = wn * 64 + bt * 8 + (lane & 3) * 2;
            float b0 = bias_s[cL], b1 = bias_s[cL + 1];
            float v0 = d[0] + b0, v1 = d[1] + b1;
            float v2 = d[2] + b0, v3 = d[3] + b1;
            sslo += v0 * v0 + v1 * v1;
            sshi += v2 * v2 + v3 * v3;
            if (n0 < N) *(float2*)(out + ((size_t)h * N + n0) * DST + cL) = make_float2(v0, v1);
            if (n1 < N) *(float2*)(out + ((size_t)h * N + n1) * DST + cL) = make_float2(v2, v3);
        }
        atomicAdd(&ssbuf[rL], sslo);
        atomicAdd(&ssbuf[rL + 8], sshi);
    }
    __syncthreads();
    if (tid < 64) {
        int n = r0 + tid;
        if (n < N)
            out[((size_t)h * N + n) * DST + DS] = sqrtf(1.f + ssbuf[tid]);
    }
}

// ---------------- phi = exp(space @ proj / sqrt(tau)) * front ----------------
__global__ __launch_bounds__(256) void phi_kernel(int in_sel, const float* __restrict__ proj,
                                                  int out_sel, int N)
{
    const float* hyp = bufp(in_sel);
    float* phi = bufp(out_sel);
    const int h  = blockIdx.y;
    const int r0 = blockIdx.x * 128;
    const int tid = threadIdx.x;
    const int tx = tid & 15, ty = tid >> 4;

    __shared__ __align__(16) float As[2][16][132];
    __shared__ __align__(16) float Bs[2][16][64];

    float acc[8][4];
#pragma unroll
    for (int i = 0; i < 8; i++)
#pragma unroll
        for (int j = 0; j < 4; j++) acc[i][j] = 0.f;

    float  ra[8];
    float4 rb;
    {
#pragma unroll
        for (int j = 0; j < 8; j++) {
            int f = tid + j * 256;
            int kk = f & 15, row = f >> 4;
            int n = r0 + row;
            As[0][kk][row] = (n < N) ? hyp[((size_t)h * N + n) * DST + kk] : 0.f;
        }
        int kk = tid >> 4, c4 = tid & 15;
        *(float4*)&Bs[0][kk][c4 * 4] = *(const float4*)(proj + (size_t)kk * MRF + c4 * 4);
    }
    __syncthreads();

    const int NCH = DS / 16;
    for (int c = 0; c < NCH; c++) {
        int cur = c & 1;
        if (c + 1 < NCH) {
            int k0 = (c + 1) * 16;
#pragma unroll
            for (int j = 0; j < 8; j++) {
                int f = tid + j * 256;
                int kk = f & 15, row = f >> 4;
                int n = r0 + row;
                ra[j] = (n < N) ? hyp[((size_t)h * N + n) * DST + k0 + kk] : 0.f;
            }
            int kk = tid >> 4, c4 = tid & 15;
            rb = *(const float4*)(proj + (size_t)(k0 + kk) * MRF + c4 * 4);
        }
#pragma unroll
        for (int kk = 0; kk < 16; kk++) {
            float4 a0 = *(const float4*)&As[cur][kk][ty * 8];
            float4 a1 = *(const float4*)&As[cur][kk][ty * 8 + 4];
            float4 b  = *(const float4*)&Bs[cur][kk][tx * 4];
            float av[8] = {a0.x, a0.y, a0.z, a0.w, a1.x, a1.y, a1.z, a1.w};
#pragma unroll
            for (int i = 0; i < 8; i++) {
                acc[i][0] += av[i] * b.x;
                acc[i][1] += av[i] * b.y;
                acc[i][2] += av[i] * b.z;
                acc[i][3] += av[i] * b.w;
            }
        }
        if (c + 1 < NCH) {
            __syncthreads();
            int nxt = 1 - cur;
#pragma unroll
            for (int j = 0; j < 8; j++) {
                int f = tid + j * 256;
                As[nxt][f & 15][f >> 4] = ra[j];
            }
            int kk = tid >> 4, c4 = tid & 15;
            *(float4*)&Bs[nxt][kk][c4 * 4] = rb;
            __syncthreads();
        }
    }

    const float SQT = 1.41421356237309515f;
#pragma unroll
    for (int i = 0; i < 8; i++) {
        int n = r0 + ty * 8 + i;
        if (n < N) {
            float t = hyp[((size_t)h * N + n) * DST + DS];
            float front = __expf(1.f - t * t) * 0.0625f + 1e-8f;
            float4 o;
            o.x = __expf(acc[i][0] * SQT) * front;
            o.y = __expf(acc[i][1] * SQT) * front;
            o.z = __expf(acc[i][2] * SQT) * front;
            o.w = __expf(acc[i][3] * SQT) * front;
            *(float4*)(phi + ((size_t)h * N + n) * MRF + tx * 4) = o;
        }
    }
}

// ---------------- last[h,m,d] = sum_n phi[h,n,m] * val[h,n,d] ----------------
__global__ __launch_bounds__(256) void last_kernel(int phi_sel, int val_sel, int out_sel,
                                                   int N, int chunkRows)
{
    const float* ph  = bufp(phi_sel);
    const float* val = bufp(val_sel);
    float* lb = bufp(out_sel);
    const int d0 = blockIdx.x * 64;
    const int h  = blockIdx.y;
    const int n0 = blockIdx.z * chunkRows;
    const int tid = threadIdx.x;
    const int tx = tid & 15, ty = tid >> 4;
    const int nEnd = min(n0 + chunkRows, N);

    __shared__ __align__(16) float Ps[2][16][68];
    __shared__ __align__(16) float Vs[2][16][68];

    float acc[4][4];
#pragma unroll
    for (int i = 0; i < 4; i++)
#pragma unroll
        for (int j = 0; j < 4; j++) acc[i][j] = 0.f;

    const int kk = tid >> 4;
    const int q4 = tid & 15;

    float4 rp;
    float  rv[4];
    {
        int n = n0 + kk;
        rp = (n < nEnd) ? *(const float4*)(ph + ((size_t)h * N + n) * MRF + q4 * 4)
                        : make_float4(0.f, 0.f, 0.f, 0.f);
        *(float4*)&Ps[0][kk][q4 * 4] = rp;
#pragma unroll
        for (int jj = 0; jj < 4; jj++) {
            int d = d0 + q4 * 4 + jj;
            Vs[0][kk][q4 * 4 + jj] = (n < nEnd && d < DIN)
                ? val[((size_t)h * N + n) * DST + d] : 0.f;
        }
    }
    __syncthreads();

    const int steps = (chunkRows + 15) / 16;
    for (int s = 0; s < steps; s++) {
        int cur = s & 1;
        if (s + 1 < steps) {
            int n = n0 + (s + 1) * 16 + kk;
            rp = (n < nEnd) ? *(const float4*)(ph + ((size_t)h * N + n) * MRF + q4 * 4)
                            : make_float4(0.f, 0.f, 0.f, 0.f);
#pragma unroll
            for (int jj = 0; jj < 4; jj++) {
                int d = d0 + q4 * 4 + jj;
                rv[jj] = (n < nEnd && d < DIN) ? val[((size_t)h * N + n) * DST + d] : 0.f;
            }
        }
#pragma unroll
        for (int k = 0; k < 16; k++) {
            float4 p = *(const float4*)&Ps[cur][k][ty * 4];
            float4 v = *(const float4*)&Vs[cur][k][tx * 4];
            float pv[4] = {p.x, p.y, p.z, p.w};
            float vv[4] = {v.x, v.y, v.z, v.w};
#pragma unroll
            for (int i = 0; i < 4; i++)
#pragma unroll
                for (int j = 0; j < 4; j++) acc[i][j] += pv[i] * vv[j];
        }
        if (s + 1 < steps) {
            __syncthreads();
            int nxt = 1 - cur;
            *(float4*)&Ps[nxt][kk][q4 * 4] = rp;
#pragma unroll
            for (int jj = 0; jj < 4; jj++) Vs[nxt][kk][q4 * 4 + jj] = rv[jj];
            __syncthreads();
        }
    }

#pragma unroll
    for (int i = 0; i < 4; i++)
#pragma unroll
        for (int j = 0; j < 4; j++) {
            int d = d0 + tx * 4 + j;
            if (d < DIN)
                atomicAdd(&lb[((size_t)h * MRF + ty * 4 + i) * DIN + d], acc[i][j]);
        }
}

// ---------------- z[h,n,:] = phi_q[h,n,:] @ last[h] ----------------
__global__ __launch_bounds__(256) void z_kernel(int phi_sel, int last_sel, int out_sel, int N)
{
    extern __shared__ __align__(16) float sh[];
    const float* phiq = bufp(phi_sel);
    const float* lb   = bufp(last_sel);
    float* z = bufp(out_sel);
    const int h = blockIdx.y;
    const int tid = threadIdx.x;

    for (int idx = tid; idx < MRF * DIN; idx += 256) {
        int m = idx / DIN;
        int d = idx - m * DIN;
        sh[m * 260 + d] = lb[(size_t)h * MRF * DIN + idx];
    }
    __syncthreads();

    int n = blockIdx.x * 256 + tid;
    if (n >= N) return;

    float q[64];
    const float* qp = phiq + ((size_t)h * N + n) * MRF;
#pragma unroll
    for (int m4 = 0; m4 < 16; m4++) {
        float4 v = *(const float4*)(qp + m4 * 4);
        q[m4 * 4 + 0] = v.x; q[m4 * 4 + 1] = v.y;
        q[m4 * 4 + 2] = v.z; q[m4 * 4 + 3] = v.w;
    }

    float* zr = z + ((size_t)h * N + n) * DST;
    for (int d4 = 0; d4 < 64; d4++) {
        float ax = 0.f, ay = 0.f, az = 0.f, aw = 0.f;
#pragma unroll
        for (int m = 0; m < 64; m++) {
            float4 L = *(const float4*)&sh[m * 260 + d4 * 4];
            ax += q[m] * L.x; ay += q[m] * L.y;
            az += q[m] * L.z; aw += q[m] * L.w;
        }
        *(float4*)(zr + d4 * 4) = make_float4(ax, ay, az, aw);
    }
    float at = 0.f;
#pragma unroll
    for (int m = 0; m < 64; m++) at += q[m] * sh[m * 260 + 256];
    zr[256] = at;
}

// ---------------- finalize ----------------
__global__ __launch_bounds__(256) void final_kernel(int val_sel, int z_sel,
                                                    float* __restrict__ out, int N)
{
    const float* val = bufp(val_sel);
    const float* zb  = bufp(z_sel);
    const int warp = threadIdx.x >> 5;
    const int lane = threadIdx.x & 31;
    const int n = blockIdx.x * 8 + warp;
    if (n >= N) return;

    float mean[9];
#pragma unroll
    for (int jj = 0; jj < 9; jj++) mean[jj] = 0.f;

    for (int h = 0; h < HN; h++) {
        const float* zr = zb  + ((size_t)h * N + n) * DST;
        const float* ar = val + ((size_t)h * N + n) * DST;
        float zv[9], av[9];
        float mq = 0.f;
#pragma unroll
        for (int jj = 0; jj < 9; jj++) {
            int d = lane + jj * 32;
            bool ok = d < DIN;
            float zz = ok ? zr[d] : 0.f;
            float aa = ok ? ar[d] : 0.f;
            zv[jj] = zz; av[jj] = aa;
            mq += zz * zz * ((d == DS) ? -1.f : 1.f);
        }
        mq = wsum(mq);
        float coeff = rsqrtf(fabsf(mq + 1e-7f));
        float ab = 0.f, a2 = 0.f, b2 = 0.f;
#pragma unroll
        for (int jj = 0; jj < 9; jj++) {
            float b = zv[jj] * coeff;
            zv[jj] = b;
            ab += av[jj] * b;
            a2 += av[jj] * av[jj];
            b2 += b * b;
        }
        ab = wsum(ab); a2 = wsum(a2); b2 = wsum(b2);
        float t1  = 1.f + 2.f * ab + b2;
        float t2  = 1.f - a2;
        float inv = 1.f / (1.f + 2.f * ab + a2 * b2 + 1e-7f);
#pragma unroll
        for (int jj = 0; jj < 9; jj++)
            mean[jj] += 0.25f * (t1 * av[jj] + t2 * zv[jj]) * inv;
    }

    float mq = 0.f;
#pragma unroll
    for (int jj = 0; jj < 9; jj++) {
        int d = lane + jj * 32;
        if (d < DIN) mq += mean[jj] * mean[jj] * ((d == DS) ? -1.f : 1.f);
    }
    mq = wsum(mq);
    float cf = rsqrtf(fabsf(mq) + 1e-7f);
#pragma unroll
    for (int jj = 0; jj < 9; jj++) {
        int d = lane + jj * 32;
        if (d < DIN) {
            int pos = (d == DS) ? 0 : (d + 1);
            out[(size_t)n * DIN + pos] = mean[jj] * cf;
        }
    }
}

// ---------------- launch ----------------
extern "C" void kernel_launch(void* const* d_in, const int* in_sizes, int n_in,
                              void* d_out, int out_size)
{
    const float* u    = (const float*)d_in[0];
    const float* iT   = (const float*)d_in[1];
    const float* Wk   = (const float*)d_in[2];
    const float* bk   = (const float*)d_in[3];
    const float* Wq   = (const float*)d_in[4];
    const float* bq   = (const float*)d_in[5];
    const float* Wv   = (const float*)d_in[6];
    const float* bv   = (const float*)d_in[7];
    const float* proj = (const float*)d_in[8];
    float* out = (float*)d_out;
    const int N = in_sizes[0] / DIN;   // 20000

    cudaFuncSetAttribute(z_kernel, cudaFuncAttributeMaxDynamicSharedMemorySize,
                         MRF * 260 * (int)sizeof(float));
    cudaFuncSetAttribute(hyp_mma_kernel, cudaFuncAttributeMaxDynamicSharedMemorySize,
                         SM_HYP_TOTAL);

    dim3 bh(256);
    dim3 gm((N + 63) / 64, HN);          // hyp_mma grid: 313 x 4
    dim3 gp((N + 127) / 128, HN);
    const int splits = 25;
    int chunkRows = (N + splits - 1) / splits;
    chunkRows = ((chunkRows + 15) / 16) * 16;
    dim3 gl(5, HN, splits);
    dim3 gz((N + 255) / 256, HN);
    dim3 gf((N + 7) / 8);
    const int zsm = MRF * 260 * (int)sizeof(float);

    // converts (selector-based; no symbol address lookups)
    int cx = (N * KP + 255) / 256;
    convert_x_kernel<<<cx, 256>>>(u,  0, N);
    convert_x_kernel<<<cx, 256>>>(iT, 1, N);
    int cw = (HN * 256 * KP + 255) / 256;
    convert_w_kernel<<<cw, 256>>>(Wk, 0);
    convert_w_kernel<<<cw, 256>>>(Wq, 1);
    convert_w_kernel<<<cw, 256>>>(Wv, 2);

    zero_last_kernel<<<(HN * MRF * DIN + 255) / 256, 256>>>();

    // hyp linears via mma.sync (xsel: 0=u 1=i; wmat: 0=Wk 1=Wq 2=Wv)
    hyp_mma_kernel<<<gm, bh, SM_HYP_TOTAL>>>(0, 2, bv, 0, N);   // val_u
    hyp_mma_kernel<<<gm, bh, SM_HYP_TOTAL>>>(1, 2, bv, 1, N);   // val_i
    hyp_mma_kernel<<<gm, bh, SM_HYP_TOTAL>>>(0, 1, bq, 2, N);   // u_query
    phi_kernel<<<gp, bh>>>(2, proj, 4, N);                       // phi_uq
    hyp_mma_kernel<<<gm, bh, SM_HYP_TOTAL>>>(1, 0, bk, 2, N);   // i_key
    phi_kernel<<<gp, bh>>>(2, proj, 5, N);                       // phi_ik
    hyp_mma_kernel<<<gm, bh, SM_HYP_TOTAL>>>(1, 1, bq, 2, N);   // i_query
    phi_kernel<<<gp, bh>>>(2, proj, 6, N);                       // phi_iq
    hyp_mma_kernel<<<gm, bh, SM_HYP_TOTAL>>>(0, 0, bk, 2, N);   // u_key
    phi_kernel<<<gp, bh>>>(2, proj, 7, N);                       // phi_uk

    last_kernel<<<gl, bh>>>(5, 1, 8, N, chunkRows);    // last_u = phi_ik^T @ val_i
    last_kernel<<<gl, bh>>>(7, 0, 9, N, chunkRows);    // last_i = phi_uk^T @ val_u

    z_kernel<<<gz, bh, zsm>>>(4, 8, 2, N);             // z_u -> tmp
    z_kernel<<<gz, bh, zsm>>>(6, 9, 3, N);             // z_i

    final_kernel<<<gf, bh>>>(0, 2, out, N);
    final_kernel<<<gf, bh>>>(1, 3, out + (size_t)N * DIN, N);
}

// round 9
// speedup vs baseline: 1.8505x; 1.2451x over previous
#include <cuda_runtime.h>
#include <cuda_bf16.h>
#include <cstdint>
#include <math.h>

#define HN   4
#define DIN  257
#define DS   256
#define DST  260      // internal padded row: [0..255]=space, [256]=time
#define MRF  64
#define NMAX 20000
#define KP   288      // K padded for hyp MMA (257 -> 288 zeros), 9 stages of 32
#define NSTG 9
#define ZND  288      // z N-dim padded (257 -> 288)

// ---------------- scratch ----------------
__device__ float g_val_u [(size_t)HN * NMAX * DST];
__device__ float g_val_i [(size_t)HN * NMAX * DST];
__device__ float g_tmp   [(size_t)HN * NMAX * DST];   // z_u output
__device__ float g_z_i   [(size_t)HN * NMAX * DST];
__device__ float g_phi_ik[(size_t)HN * NMAX * MRF];   // fp32 phi for last
__device__ float g_phi_uk[(size_t)HN * NMAX * MRF];
__device__ float g_last_u[HN * MRF * DIN];
__device__ float g_last_i[HN * MRF * DIN];
__device__ float g_time  [(size_t)HN * NMAX];

// bf16 split buffers
__device__ __nv_bfloat16 g_xh_u[(size_t)NMAX * KP];
__device__ __nv_bfloat16 g_xl_u[(size_t)NMAX * KP];
__device__ __nv_bfloat16 g_xh_i[(size_t)NMAX * KP];
__device__ __nv_bfloat16 g_xl_i[(size_t)NMAX * KP];
__device__ __nv_bfloat16 g_wh[3][(size_t)HN * 256 * KP];
__device__ __nv_bfloat16 g_wl[3][(size_t)HN * 256 * KP];
__device__ __nv_bfloat16 g_sh[(size_t)HN * NMAX * 256];   // space split (qk reuse)
__device__ __nv_bfloat16 g_sl[(size_t)HN * NMAX * 256];
__device__ __nv_bfloat16 g_pjh[64 * 256];                  // projT split [m][k]
__device__ __nv_bfloat16 g_pjl[64 * 256];
__device__ __nv_bfloat16 g_phbh[2][(size_t)HN * NMAX * MRF];  // phi split (uq=0, iq=1)
__device__ __nv_bfloat16 g_phbl[2][(size_t)HN * NMAX * MRF];
__device__ __nv_bfloat16 g_lth[2][(size_t)HN * ZND * MRF];    // lastT split [d][m]
__device__ __nv_bfloat16 g_ltl[2][(size_t)HN * ZND * MRF];

__device__ __forceinline__ float* bufp(int s) {
    switch (s) {
        case 0: return g_val_u;  case 1: return g_val_i;
        case 2: return g_tmp;    case 3: return g_z_i;
        case 5: return g_phi_ik; case 7: return g_phi_uk;
        case 8: return g_last_u; default: return g_last_i;
    }
}
__device__ __forceinline__ __nv_bfloat16* xhp(int s) { return s ? g_xh_i : g_xh_u; }
__device__ __forceinline__ __nv_bfloat16* xlp(int s) { return s ? g_xl_i : g_xl_u; }

__device__ __forceinline__ float wsum(float v) {
#pragma unroll
    for (int m = 16; m >= 1; m >>= 1) v += __shfl_xor_sync(0xffffffffu, v, m);
    return v;
}
__device__ __forceinline__ uint32_t smem_u32(const void* p) {
    uint32_t a;
    asm("{ .reg .u64 t; cvta.to.shared.u64 t, %1; cvt.u32.u64 %0, t; }" : "=r"(a) : "l"(p));
    return a;
}
__device__ __forceinline__ void cp16(uint32_t sa, const void* g) {
    asm volatile("cp.async.cg.shared.global [%0], [%1], 16;" :: "r"(sa), "l"(g));
}

#define LDSM_X4(r, addr)                                                           \
    asm volatile("ldmatrix.sync.aligned.m8n8.x4.shared.b16 {%0,%1,%2,%3}, [%4];"   \
        : "=r"((r)[0]), "=r"((r)[1]), "=r"((r)[2]), "=r"((r)[3]) : "r"(addr))
#define LDSM_X2(r, addr)                                                           \
    asm volatile("ldmatrix.sync.aligned.m8n8.x2.shared.b16 {%0,%1}, [%2];"         \
        : "=r"((r)[0]), "=r"((r)[1]) : "r"(addr))
#define MMA16816(d, a, b)                                                          \
    asm volatile("mma.sync.aligned.m16n8k16.row.col.f32.bf16.bf16.f32 "            \
        "{%0,%1,%2,%3},{%4,%5,%6,%7},{%8,%9},{%0,%1,%2,%3};"                       \
        : "+f"((d)[0]), "+f"((d)[1]), "+f"((d)[2]), "+f"((d)[3])                   \
        : "r"((a)[0]), "r"((a)[1]), "r"((a)[2]), "r"((a)[3]),                      \
          "r"((b)[0]), "r"((b)[1]))

// ---- hyp smem layout ----
#define STG_BYTES 40960
#define OFF_AL 4096
#define OFF_BH 8192
#define OFF_BL 24576
#define SM_BIAS_OFF (2 * STG_BYTES)
#define SM_SS_OFF   (SM_BIAS_OFF + 1024)
#define SM_HYP_TOTAL (SM_SS_OFF + 256)

// ---- phi smem layout: 2 stages of (Ah 8192|Al 8192|Bh 4096|Bl 4096) ----
#define PH_STG 24576
#define PH_AL 8192
#define PH_BH 16384
#define PH_BL 20480
#define PH_TOTAL (2 * PH_STG)     // 49152

// ---- z smem layout (single shot, K=64 -> 128B rows) ----
#define Z_AH 0
#define Z_AL 16384
#define Z_BH 32768
#define Z_BL 69632
#define Z_TOTAL 106496

// ---------------- converts ----------------
__global__ void convert_x_kernel(const float* __restrict__ x, int xsel, int N) {
    __nv_bfloat16* xh = xhp(xsel);
    __nv_bfloat16* xl = xlp(xsel);
    int idx = blockIdx.x * blockDim.x + threadIdx.x;
    if (idx >= N * KP) return;
    int n = idx / KP, k = idx - n * KP;
    float v = (k < DIN) ? x[(size_t)n * DIN + k] : 0.f;
    __nv_bfloat16 h = __float2bfloat16(v);
    __nv_bfloat16 l = __float2bfloat16(v - __bfloat162float(h));
    xh[idx] = h; xl[idx] = l;
}

__global__ void convert_w_kernel(const float* __restrict__ W, int m) {
    __nv_bfloat16* wh = g_wh[m];
    __nv_bfloat16* wl = g_wl[m];
    int idx = blockIdx.x * blockDim.x + threadIdx.x;
    if (idx >= HN * 256 * KP) return;
    int h = idx / (256 * KP);
    int r = idx - h * 256 * KP;
    int j = r / KP, k = r - j * KP;
    float v = (k < DIN) ? W[((size_t)h * DIN + k) * DS + j] : 0.f;
    __nv_bfloat16 hi = __float2bfloat16(v);
    __nv_bfloat16 lo = __float2bfloat16(v - __bfloat162float(hi));
    wh[idx] = hi; wl[idx] = lo;
}

__global__ void convert_proj_kernel(const float* __restrict__ proj) {
    int idx = blockIdx.x * blockDim.x + threadIdx.x;   // m*256 + k
    if (idx >= 64 * 256) return;
    int m = idx >> 8, k = idx & 255;
    float v = proj[(size_t)k * MRF + m];
    __nv_bfloat16 hi = __float2bfloat16(v);
    g_pjh[idx] = hi;
    g_pjl[idx] = __float2bfloat16(v - __bfloat162float(hi));
}

__global__ void zero_last_kernel() {
    int idx = blockIdx.x * blockDim.x + threadIdx.x;
    if (idx < HN * MRF * DIN) { g_last_u[idx] = 0.f; g_last_i[idx] = 0.f; }
}

// fp32 last [h][m][d] -> bf16 split lastT [h][d(288 pad)][m]
__global__ void last_split_kernel(int insel, int slot) {
    const float* lb = bufp(insel);
    int idx = blockIdx.x * blockDim.x + threadIdx.x;   // h*ZND*64 + d*64 + m
    if (idx >= HN * ZND * MRF) return;
    int h = idx / (ZND * MRF);
    int r = idx - h * ZND * MRF;
    int d = r / MRF, m = r - d * MRF;
    float v = (d < DIN) ? lb[((size_t)h * MRF + m) * DIN + d] : 0.f;
    __nv_bfloat16 hi = __float2bfloat16(v);
    g_lth[slot][idx] = hi;
    g_ltl[slot][idx] = __float2bfloat16(v - __bfloat162float(hi));
}

// ---------------- hyp_linear via mma.sync (split-bf16 3-term) ----------------
// mode 0: fp32 out[n][DST] incl time.  mode 1: bf16 split g_sh/g_sl + g_time.
__global__ __launch_bounds__(256, 2)
void hyp_mma_kernel(int xsel, int wmat, const float* __restrict__ bias,
                    int mode, int out_sel, int N)
{
    extern __shared__ char smem[];
    const int tid = threadIdx.x, wid = tid >> 5, lane = tid & 31;
    const int h = blockIdx.y, r0 = blockIdx.x * 64;
    float* out = bufp(out_sel);
    const __nv_bfloat16* xh = xhp(xsel);
    const __nv_bfloat16* xl = xlp(xsel);
    const __nv_bfloat16* wh = g_wh[wmat] + (size_t)h * 256 * KP;
    const __nv_bfloat16* wl = g_wl[wmat] + (size_t)h * 256 * KP;

    const uint32_t sb = smem_u32(smem);
    float* bias_s = (float*)(smem + SM_BIAS_OFF);
    float* ssbuf  = (float*)(smem + SM_SS_OFF);
    if (tid < 64) ssbuf[tid] = 0.f;
    bias_s[tid] = bias[h * DS + tid];

    auto load_stage = [&](int s) {
        const int k0 = s * 32;
        const uint32_t base = sb + (s & 1) * STG_BYTES;
        {
            int row = tid >> 2, c = tid & 3;
            int n = min(r0 + row, N - 1);
            uint32_t dst = base + row * 64 + ((c ^ (row & 3)) << 4);
            cp16(dst,          xh + (size_t)n * KP + k0 + c * 8);
            cp16(dst + OFF_AL, xl + (size_t)n * KP + k0 + c * 8);
        }
#pragma unroll
        for (int i = 0; i < 4; i++) {
            int u = tid + i * 256;
            int row = u >> 2, c = u & 3;
            uint32_t dst = base + OFF_BH + row * 64 + ((c ^ (row & 3)) << 4);
            cp16(dst,                   wh + (size_t)row * KP + k0 + c * 8);
            cp16(dst + (OFF_BL-OFF_BH), wl + (size_t)row * KP + k0 + c * 8);
        }
        asm volatile("cp.async.commit_group;" ::: "memory");
    };

    float acc[16][4];
#pragma unroll
    for (int i = 0; i < 16; i++)
#pragma unroll
        for (int j = 0; j < 4; j++) acc[i][j] = 0.f;

    const int wm = wid >> 2, wn = wid & 3;

    load_stage(0);
    load_stage(1);

    for (int s = 0; s < NSTG; s++) {
        if (s + 1 < NSTG) asm volatile("cp.async.wait_group 1;" ::: "memory");
        else              asm volatile("cp.async.wait_group 0;" ::: "memory");
        __syncthreads();
        const uint32_t base = sb + (s & 1) * STG_BYTES;
#pragma unroll
        for (int kh = 0; kh < 2; kh++) {
            uint32_t ah[2][4], al[2][4];
#pragma unroll
            for (int mt = 0; mt < 2; mt++) {
                int r = wm * 32 + mt * 16 + (lane & 15);
                int ch = kh * 2 + ((lane >> 4) & 1);
                uint32_t ad = base + r * 64 + ((ch ^ (r & 3)) << 4);
                LDSM_X4(ah[mt], ad);
                LDSM_X4(al[mt], ad + OFF_AL);
            }
#pragma unroll
            for (int bt = 0; bt < 8; bt++) {
                int rr = wn * 64 + bt * 8 + (lane & 7);
                int ch = kh * 2 + ((lane >> 3) & 1);
                uint32_t bd = base + OFF_BH + rr * 64 + ((ch ^ (rr & 3)) << 4);
                uint32_t bh_[2], bl_[2];
                LDSM_X2(bh_, bd);
                LDSM_X2(bl_, bd + (OFF_BL - OFF_BH));
#pragma unroll
                for (int mt = 0; mt < 2; mt++) {
                    MMA16816(acc[mt*8+bt], ah[mt], bh_);
                    MMA16816(acc[mt*8+bt], ah[mt], bl_);
                    MMA16816(acc[mt*8+bt], al[mt], bh_);
                }
            }
        }
        __syncthreads();
        if (s + 2 < NSTG) load_stage(s + 2);
    }

    // ---- epilogue ----
#pragma unroll
    for (int mt = 0; mt < 2; mt++) {
        float sslo = 0.f, sshi = 0.f;
        int rL = wm * 32 + mt * 16 + (lane >> 2);
        int n0 = r0 + rL, n1 = n0 + 8;
#pragma unroll
        for (int bt = 0; bt < 8; bt++) {
            float* d = acc[mt*8+bt];
            int cL = wn * 64 + bt * 8 + (lane & 3) * 2;
            float b0 = bias_s[cL], b1 = bias_s[cL + 1];
            float v0 = d[0] + b0, v1 = d[1] + b1;
            float v2 = d[2] + b0, v3 = d[3] + b1;
            sslo += v0 * v0 + v1 * v1;
            sshi += v2 * v2 + v3 * v3;
            if (mode == 0) {
                if (n0 < N) *(float2*)(out + ((size_t)h * N + n0) * DST + cL) = make_float2(v0, v1);
                if (n1 < N) *(float2*)(out + ((size_t)h * N + n1) * DST + cL) = make_float2(v2, v3);
            } else {
                if (n0 < N) {
                    __nv_bfloat16 h0 = __float2bfloat16(v0), h1 = __float2bfloat16(v1);
                    *(__nv_bfloat162*)(g_sh + ((size_t)h * N + n0) * 256 + cL) =
                        __nv_bfloat162{h0, h1};
                    *(__nv_bfloat162*)(g_sl + ((size_t)h * N + n0) * 256 + cL) =
                        __nv_bfloat162{__float2bfloat16(v0 - __bfloat162float(h0)),
                                       __float2bfloat16(v1 - __bfloat162float(h1))};
                }
                if (n1 < N) {
                    __nv_bfloat16 h2 = __float2bfloat16(v2), h3 = __float2bfloat16(v3);
                    *(__nv_bfloat162*)(g_sh + ((size_t)h * N + n1) * 256 + cL) =
                        __nv_bfloat162{h2, h3};
                    *(__nv_bfloat162*)(g_sl + ((size_t)h * N + n1) * 256 + cL) =
                        __nv_bfloat162{__float2bfloat16(v2 - __bfloat162float(h2)),
                                       __float2bfloat16(v3 - __bfloat162float(h3))};
                }
            }
        }
        atomicAdd(&ssbuf[rL], sslo);
        atomicAdd(&ssbuf[rL + 8], sshi);
    }
    __syncthreads();
    if (tid < 64) {
        int n = r0 + tid;
        if (n < N) {
            float t = sqrtf(1.f + ssbuf[tid]);
            if (mode == 0) out[((size_t)h * N + n) * DST + DS] = t;
            else           g_time[(size_t)h * N + n] = t;
        }
    }
}

// ---------------- phi via mma.sync ----------------
// phi[n,m] = exp(dot(space[n,:], projT[m,:]) * sqrt2) * front(t[n])
// outmode 0: fp32 to bufp(sel);  outmode 1: bf16 split to g_phbh/l[sel]
__global__ __launch_bounds__(256, 2)
void phi_mma_kernel(int outmode, int sel, int N)
{
    extern __shared__ char smem[];
    const int tid = threadIdx.x, wid = tid >> 5, lane = tid & 31;
    const int h = blockIdx.y, r0 = blockIdx.x * 128;
    const uint32_t sb = smem_u32(smem);

    auto load_stage = [&](int s) {
        const int k0 = s * 32;
        const uint32_t base = sb + (s & 1) * PH_STG;
#pragma unroll
        for (int i = 0; i < 2; i++) {
            int u = tid + i * 256;
            int row = u >> 2, c = u & 3;
            int n = min(r0 + row, N - 1);
            uint32_t dst = base + row * 64 + ((c ^ (row & 3)) << 4);
            cp16(dst,         g_sh + ((size_t)h * N + n) * 256 + k0 + c * 8);
            cp16(dst + PH_AL, g_sl + ((size_t)h * N + n) * 256 + k0 + c * 8);
        }
        {
            int row = tid >> 2, c = tid & 3;
            uint32_t dst = base + PH_BH + row * 64 + ((c ^ (row & 3)) << 4);
            cp16(dst,                 g_pjh + (size_t)row * 256 + k0 + c * 8);
            cp16(dst + (PH_BL-PH_BH), g_pjl + (size_t)row * 256 + k0 + c * 8);
        }
        asm volatile("cp.async.commit_group;" ::: "memory");
    };

    float acc[8][4];
#pragma unroll
    for (int i = 0; i < 8; i++)
#pragma unroll
        for (int j = 0; j < 4; j++) acc[i][j] = 0.f;

    const int wm = wid >> 1, wn = wid & 1;   // rows wm*32, cols wn*32

    load_stage(0);
    load_stage(1);

    for (int s = 0; s < 8; s++) {
        if (s + 1 < 8) asm volatile("cp.async.wait_group 1;" ::: "memory");
        else           asm volatile("cp.async.wait_group 0;" ::: "memory");
        __syncthreads();
        const uint32_t base = sb + (s & 1) * PH_STG;
#pragma unroll
        for (int kh = 0; kh < 2; kh++) {
            uint32_t ah[2][4], al[2][4];
#pragma unroll
            for (int mt = 0; mt < 2; mt++) {
                int r = wm * 32 + mt * 16 + (lane & 15);
                int ch = kh * 2 + ((lane >> 4) & 1);
                uint32_t ad = base + r * 64 + ((ch ^ (r & 3)) << 4);
                LDSM_X4(ah[mt], ad);
                LDSM_X4(al[mt], ad + PH_AL);
            }
#pragma unroll
            for (int bt = 0; bt < 4; bt++) {
                int rr = wn * 32 + bt * 8 + (lane & 7);
                int ch = kh * 2 + ((lane >> 3) & 1);
                uint32_t bd = base + PH_BH + rr * 64 + ((ch ^ (rr & 3)) << 4);
                uint32_t bh_[2], bl_[2];
                LDSM_X2(bh_, bd);
                LDSM_X2(bl_, bd + (PH_BL - PH_BH));
#pragma unroll
                for (int mt = 0; mt < 2; mt++) {
                    MMA16816(acc[mt*4+bt], ah[mt], bh_);
                    MMA16816(acc[mt*4+bt], ah[mt], bl_);
                    MMA16816(acc[mt*4+bt], al[mt], bh_);
                }
            }
        }
        __syncthreads();
        if (s + 2 < 8) load_stage(s + 2);
    }

    const float SQT = 1.41421356237309515f;
    float* outf = bufp(sel);
    __nv_bfloat16* obh = g_phbh[sel & 1];
    __nv_bfloat16* obl = g_phbl[sel & 1];
#pragma unroll
    for (int mt = 0; mt < 2; mt++) {
        int n0 = r0 + wm * 32 + mt * 16 + (lane >> 2), n1 = n0 + 8;
        float fr0 = 0.f, fr1 = 0.f;
        if (n0 < N) { float t = g_time[(size_t)h * N + n0]; fr0 = __expf(1.f - t*t) * 0.0625f + 1e-8f; }
        if (n1 < N) { float t = g_time[(size_t)h * N + n1]; fr1 = __expf(1.f - t*t) * 0.0625f + 1e-8f; }
#pragma unroll
        for (int bt = 0; bt < 4; bt++) {
            float* d = acc[mt*4+bt];
            int cL = wn * 32 + bt * 8 + (lane & 3) * 2;
            float o0 = __expf(d[0] * SQT) * fr0;
            float o1 = __expf(d[1] * SQT) * fr0;
            float o2 = __expf(d[2] * SQT) * fr1;
            float o3 = __expf(d[3] * SQT) * fr1;
            if (outmode == 0) {
                if (n0 < N) *(float2*)(outf + ((size_t)h * N + n0) * MRF + cL) = make_float2(o0, o1);
                if (n1 < N) *(float2*)(outf + ((size_t)h * N + n1) * MRF + cL) = make_float2(o2, o3);
            } else {
                if (n0 < N) {
                    __nv_bfloat16 h0 = __float2bfloat16(o0), h1 = __float2bfloat16(o1);
                    *(__nv_bfloat162*)(obh + ((size_t)h * N + n0) * MRF + cL) = __nv_bfloat162{h0, h1};
                    *(__nv_bfloat162*)(obl + ((size_t)h * N + n0) * MRF + cL) =
                        __nv_bfloat162{__float2bfloat16(o0 - __bfloat162float(h0)),
                                       __float2bfloat16(o1 - __bfloat162float(h1))};
                }
                if (n1 < N) {
                    __nv_bfloat16 h2 = __float2bfloat16(o2), h3 = __float2bfloat16(o3);
                    *(__nv_bfloat162*)(obh + ((size_t)h * N + n1) * MRF + cL) = __nv_bfloat162{h2, h3};
                    *(__nv_bfloat162*)(obl + ((size_t)h * N + n1) * MRF + cL) =
                        __nv_bfloat162{__float2bfloat16(o2 - __bfloat162float(h2)),
                                       __float2bfloat16(o3 - __bfloat162float(h3))};
                }
            }
        }
    }
}

// ---------------- last[h,m,d] = sum_n phi[h,n,m] * val[h,n,d] (SIMT) ----------------
__global__ __launch_bounds__(256) void last_kernel(int phi_sel, int val_sel, int out_sel,
                                                   int N, int chunkRows)
{
    const float* ph  = bufp(phi_sel);
    const float* val = bufp(val_sel);
    float* lb = bufp(out_sel);
    const int d0 = blockIdx.x * 64;
    const int h  = blockIdx.y;
    const int n0 = blockIdx.z * chunkRows;
    const int tid = threadIdx.x;
    const int tx = tid & 15, ty = tid >> 4;
    const int nEnd = min(n0 + chunkRows, N);

    __shared__ __align__(16) float Ps[2][16][68];
    __shared__ __align__(16) float Vs[2][16][68];

    float acc[4][4];
#pragma unroll
    for (int i = 0; i < 4; i++)
#pragma unroll
        for (int j = 0; j < 4; j++) acc[i][j] = 0.f;

    const int kk = tid >> 4;
    const int q4 = tid & 15;

    float4 rp;
    float  rv[4];
    {
        int n = n0 + kk;
        rp = (n < nEnd) ? *(const float4*)(ph + ((size_t)h * N + n) * MRF + q4 * 4)
                        : make_float4(0.f, 0.f, 0.f, 0.f);
        *(float4*)&Ps[0][kk][q4 * 4] = rp;
#pragma unroll
        for (int jj = 0; jj < 4; jj++) {
            int d = d0 + q4 * 4 + jj;
            Vs[0][kk][q4 * 4 + jj] = (n < nEnd && d < DIN)
                ? val[((size_t)h * N + n) * DST + d] : 0.f;
        }
    }
    __syncthreads();

    const int steps = (chunkRows + 15) / 16;
    for (int s = 0; s < steps; s++) {
        int cur = s & 1;
        if (s + 1 < steps) {
            int n = n0 + (s + 1) * 16 + kk;
            rp = (n < nEnd) ? *(const float4*)(ph + ((size_t)h * N + n) * MRF + q4 * 4)
                            : make_float4(0.f, 0.f, 0.f, 0.f);
#pragma unroll
            for (int jj = 0; jj < 4; jj++) {
                int d = d0 + q4 * 4 + jj;
                rv[jj] = (n < nEnd && d < DIN) ? val[((size_t)h * N + n) * DST + d] : 0.f;
            }
        }
#pragma unroll
        for (int k = 0; k < 16; k++) {
            float4 p = *(const float4*)&Ps[cur][k][ty * 4];
            float4 v = *(const float4*)&Vs[cur][k][tx * 4];
            float pv[4] = {p.x, p.y, p.z, p.w};
            float vv[4] = {v.x, v.y, v.z, v.w};
#pragma unroll
            for (int i = 0; i < 4; i++)
#pragma unroll
                for (int j = 0; j < 4; j++) acc[i][j] += pv[i] * vv[j];
        }
        if (s + 1 < steps) {
            __syncthreads();
            int nxt = 1 - cur;
            *(float4*)&Ps[nxt][kk][q4 * 4] = rp;
#pragma unroll
            for (int jj = 0; jj < 4; jj++) Vs[nxt][kk][q4 * 4 + jj] = rv[jj];
            __syncthreads();
        }
    }

#pragma unroll
    for (int i = 0; i < 4; i++)
#pragma unroll
        for (int j = 0; j < 4; j++) {
            int d = d0 + tx * 4 + j;
            if (d < DIN)
                atomicAdd(&lb[((size_t)h * MRF + ty * 4 + i) * DIN + d], acc[i][j]);
        }
}

// ---------------- z via mma.sync: z[n,d] = sum_m phi[n,m] lastT[d,m] ----------------
__global__ __launch_bounds__(256)
void z_mma_kernel(int slot, int out_sel, int N)
{
    extern __shared__ char smem[];
    const int tid = threadIdx.x, wid = tid >> 5, lane = tid & 31;
    const int h = blockIdx.y, r0 = blockIdx.x * 128;
    const uint32_t sb = smem_u32(smem);
    float* zb = bufp(out_sel);
    const __nv_bfloat16* ah_g = g_phbh[slot];
    const __nv_bfloat16* al_g = g_phbl[slot];
    const __nv_bfloat16* bh_g = g_lth[slot];
    const __nv_bfloat16* bl_g = g_ltl[slot];

    // load A: 128 rows x 8 chunks (K=64, 128B rows)
#pragma unroll
    for (int i = 0; i < 4; i++) {
        int u = tid + i * 256;
        int row = u >> 3, c = u & 7;
        int n = min(r0 + row, N - 1);
        uint32_t dst = sb + Z_AH + row * 128 + ((c ^ (row & 7)) << 4);
        cp16(dst,               ah_g + ((size_t)h * N + n) * MRF + c * 8);
        cp16(dst + (Z_AL-Z_AH), al_g + ((size_t)h * N + n) * MRF + c * 8);
    }
    // load B: 288 rows x 8 chunks
#pragma unroll
    for (int i = 0; i < 9; i++) {
        int u = tid + i * 256;
        int row = u >> 3, c = u & 7;
        uint32_t dst = sb + Z_BH + row * 128 + ((c ^ (row & 7)) << 4);
        cp16(dst,               bh_g + ((size_t)h * ZND + row) * MRF + c * 8);
        cp16(dst + (Z_BL-Z_BH), bl_g + ((size_t)h * ZND + row) * MRF + c * 8);
    }
    asm volatile("cp.async.commit_group;" ::: "memory");
    asm volatile("cp.async.wait_group 0;" ::: "memory");
    __syncthreads();

    float acc[36][4];
#pragma unroll
    for (int i = 0; i < 36; i++)
#pragma unroll
        for (int j = 0; j < 4; j++) acc[i][j] = 0.f;

    const int wm = wid >> 2, wn = wid & 3;   // rows wm*64 (4 mt), cols wn*72 (9 bt)

#pragma unroll
    for (int kh = 0; kh < 4; kh++) {
        uint32_t ah[4][4], al[4][4];
#pragma unroll
        for (int mt = 0; mt < 4; mt++) {
            int r = wm * 64 + mt * 16 + (lane & 15);
            int ch = kh * 2 + ((lane >> 4) & 1);
            uint32_t ad = sb + Z_AH + r * 128 + ((ch ^ (r & 7)) << 4);
            LDSM_X4(ah[mt], ad);
            LDSM_X4(al[mt], ad + (Z_AL - Z_AH));
        }
#pragma unroll
        for (int bt = 0; bt < 9; bt++) {
            int rr = wn * 72 + bt * 8 + (lane & 7);
            int ch = kh * 2 + ((lane >> 3) & 1);
            uint32_t bd = sb + Z_BH + rr * 128 + ((ch ^ (rr & 7)) << 4);
            uint32_t bh_[2], bl_[2];
            LDSM_X2(bh_, bd);
            LDSM_X2(bl_, bd + (Z_BL - Z_BH));
#pragma unroll
            for (int mt = 0; mt < 4; mt++) {
                MMA16816(acc[mt*9+bt], ah[mt], bh_);
                MMA16816(acc[mt*9+bt], ah[mt], bl_);
                MMA16816(acc[mt*9+bt], al[mt], bh_);
            }
        }
    }

#pragma unroll
    for (int mt = 0; mt < 4; mt++) {
        int n0 = r0 + wm * 64 + mt * 16 + (lane >> 2), n1 = n0 + 8;
#pragma unroll
        for (int bt = 0; bt < 9; bt++) {
            float* d = acc[mt*9+bt];
            int cL = wn * 72 + bt * 8 + (lane & 3) * 2;
            if (cL < 256) {
                if (n0 < N) *(float2*)(zb + ((size_t)h * N + n0) * DST + cL) = make_float2(d[0], d[1]);
                if (n1 < N) *(float2*)(zb + ((size_t)h * N + n1) * DST + cL) = make_float2(d[2], d[3]);
            } else if (cL == 256) {
                if (n0 < N) zb[((size_t)h * N + n0) * DST + 256] = d[0];
                if (n1 < N) zb[((size_t)h * N + n1) * DST + 256] = d[2];
            }
        }
    }
}

// ---------------- finalize ----------------
__global__ __launch_bounds__(256) void final_kernel(int val_sel, int z_sel,
                                                    float* __restrict__ out, int N)
{
    const float* val = bufp(val_sel);
    const float* zb  = bufp(z_sel);
    const int warp = threadIdx.x >> 5;
    const int lane = threadIdx.x & 31;
    const int n = blockIdx.x * 8 + warp;
    if (n >= N) return;

    float mean[9];
#pragma unroll
    for (int jj = 0; jj < 9; jj++) mean[jj] = 0.f;

    for (int h = 0; h < HN; h++) {
        const float* zr = zb  + ((size_t)h * N + n) * DST;
        const float* ar = val + ((size_t)h * N + n) * DST;
        float zv[9], av[9];
        float mq = 0.f;
#pragma unroll
        for (int jj = 0; jj < 9; jj++) {
            int d = lane + jj * 32;
            bool ok = d < DIN;
            float zz = ok ? zr[d] : 0.f;
            float aa = ok ? ar[d] : 0.f;
            zv[jj] = zz; av[jj] = aa;
            mq += zz * zz * ((d == DS) ? -1.f : 1.f);
        }
        mq = wsum(mq);
        float coeff = rsqrtf(fabsf(mq + 1e-7f));
        float ab = 0.f, a2 = 0.f, b2 = 0.f;
#pragma unroll
        for (int jj = 0; jj < 9; jj++) {
            float b = zv[jj] * coeff;
            zv[jj] = b;
            ab += av[jj] * b;
            a2 += av[jj] * av[jj];
            b2 += b * b;
        }
        ab = wsum(ab); a2 = wsum(a2); b2 = wsum(b2);
        float t1  = 1.f + 2.f * ab + b2;
        float t2  = 1.f - a2;
        float inv = 1.f / (1.f + 2.f * ab + a2 * b2 + 1e-7f);
#pragma unroll
        for (int jj = 0; jj < 9; jj++)
            mean[jj] += 0.25f * (t1 * av[jj] + t2 * zv[jj]) * inv;
    }

    float mq = 0.f;
#pragma unroll
    for (int jj = 0; jj < 9; jj++) {
        int d = lane + jj * 32;
        if (d < DIN) mq += mean[jj] * mean[jj] * ((d == DS) ? -1.f : 1.f);
    }
    mq = wsum(mq);
    float cf = rsqrtf(fabsf(mq) + 1e-7f);
#pragma unroll
    for (int jj = 0; jj < 9; jj++) {
        int d = lane + jj * 32;
        if (d < DIN) {
            int pos = (d == DS) ? 0 : (d + 1);
            out[(size_t)n * DIN + pos] = mean[jj] * cf;
        }
    }
}

// ---------------- launch ----------------
extern "C" void kernel_launch(void* const* d_in, const int* in_sizes, int n_in,
                              void* d_out, int out_size)
{
    const float* u    = (const float*)d_in[0];
    const float* iT   = (const float*)d_in[1];
    const float* Wk   = (const float*)d_in[2];
    const float* bk   = (const float*)d_in[3];
    const float* Wq   = (const float*)d_in[4];
    const float* bq   = (const float*)d_in[5];
    const float* Wv   = (const float*)d_in[6];
    const float* bv   = (const float*)d_in[7];
    const float* proj = (const float*)d_in[8];
    float* out = (float*)d_out;
    const int N = in_sizes[0] / DIN;   // 20000

    cudaFuncSetAttribute(hyp_mma_kernel, cudaFuncAttributeMaxDynamicSharedMemorySize, SM_HYP_TOTAL);
    cudaFuncSetAttribute(phi_mma_kernel, cudaFuncAttributeMaxDynamicSharedMemorySize, PH_TOTAL);
    cudaFuncSetAttribute(z_mma_kernel,   cudaFuncAttributeMaxDynamicSharedMemorySize, Z_TOTAL);

    dim3 bh(256);
    dim3 gm((N + 63) / 64, HN);
    dim3 gp((N + 127) / 128, HN);
    const int splits = 25;
    int chunkRows = (N + splits - 1) / splits;
    chunkRows = ((chunkRows + 15) / 16) * 16;
    dim3 gl(5, HN, splits);

    // converts
    int cx = (N * KP + 255) / 256;
    convert_x_kernel<<<cx, 256>>>(u,  0, N);
    convert_x_kernel<<<cx, 256>>>(iT, 1, N);
    int cw = (HN * 256 * KP + 255) / 256;
    convert_w_kernel<<<cw, 256>>>(Wk, 0);
    convert_w_kernel<<<cw, 256>>>(Wq, 1);
    convert_w_kernel<<<cw, 256>>>(Wv, 2);
    convert_proj_kernel<<<(64 * 256 + 255) / 256, 256>>>(proj);
    zero_last_kernel<<<(HN * MRF * DIN + 255) / 256, 256>>>();

    // values (fp32 mode)
    hyp_mma_kernel<<<gm, bh, SM_HYP_TOTAL>>>(0, 2, bv, 0, 0, N);   // val_u
    hyp_mma_kernel<<<gm, bh, SM_HYP_TOTAL>>>(1, 2, bv, 0, 1, N);   // val_i

    // queries/keys (split mode) + phi
    hyp_mma_kernel<<<gm, bh, SM_HYP_TOTAL>>>(0, 1, bq, 1, 0, N);   // u_query -> split
    phi_mma_kernel<<<gp, bh, PH_TOTAL>>>(1, 0, N);                 // phi_uq -> phb slot 0
    hyp_mma_kernel<<<gm, bh, SM_HYP_TOTAL>>>(1, 0, bk, 1, 0, N);   // i_key -> split
    phi_mma_kernel<<<gp, bh, PH_TOTAL>>>(0, 5, N);                 // phi_ik fp32
    hyp_mma_kernel<<<gm, bh, SM_HYP_TOTAL>>>(1, 1, bq, 1, 0, N);   // i_query -> split
    phi_mma_kernel<<<gp, bh, PH_TOTAL>>>(1, 1, N);                 // phi_iq -> phb slot 1
    hyp_mma_kernel<<<gm, bh, SM_HYP_TOTAL>>>(0, 0, bk, 1, 0, N);   // u_key -> split
    phi_mma_kernel<<<gp, bh, PH_TOTAL>>>(0, 7, N);                 // phi_uk fp32

    // last (SIMT, atomics)
    last_kernel<<<gl, bh>>>(5, 1, 8, N, chunkRows);    // last_u = phi_ik^T @ val_i
    last_kernel<<<gl, bh>>>(7, 0, 9, N, chunkRows);    // last_i = phi_uk^T @ val_u

    // lastT bf16 splits
    int cl = (HN * ZND * MRF + 255) / 256;
    last_split_kernel<<<cl, 256>>>(8, 0);
    last_split_kernel<<<cl, 256>>>(9, 1);

    // z via MMA
    z_mma_kernel<<<gp, bh, Z_TOTAL>>>(0, 2, N);        // z_u -> tmp
    z_mma_kernel<<<gp, bh, Z_TOTAL>>>(1, 3, N);        // z_i

    final_kernel<<<dim3((N + 7) / 8), bh>>>(0, 2, out, N);
    final_kernel<<<dim3((N + 7) / 8), bh>>>(1, 3, out + (size_t)N * DIN, N);
}

// round 10
// speedup vs baseline: 1.9377x; 1.0471x over previous
#include <cuda_runtime.h>
#include <cuda_bf16.h>
#include <cstdint>
#include <math.h>

#define HN   4
#define DIN  257
#define DS   256
#define DST  260      // internal padded row: [0..255]=space, [256]=time
#define MRF  64
#define NMAX 20000
#define KP   288      // K padded for hyp MMA (257 -> 288 zeros), 9 stages of 32
#define NSTG 9
#define ZND  288      // z N-dim padded
#define VSW  288      // val-split row width: [0..255]=space, 256=time, 257..287=0

// ---------------- scratch ----------------
__device__ float g_val_u [(size_t)HN * NMAX * DST];
__device__ float g_val_i [(size_t)HN * NMAX * DST];
__device__ float g_tmp   [(size_t)HN * NMAX * DST];   // z_u output
__device__ float g_z_i   [(size_t)HN * NMAX * DST];
__device__ float g_last_u[HN * MRF * DIN];
__device__ float g_last_i[HN * MRF * DIN];
__device__ float g_time  [(size_t)HN * NMAX];

// bf16 split buffers
__device__ __nv_bfloat16 g_xh_u[(size_t)NMAX * KP];
__device__ __nv_bfloat16 g_xl_u[(size_t)NMAX * KP];
__device__ __nv_bfloat16 g_xh_i[(size_t)NMAX * KP];
__device__ __nv_bfloat16 g_xl_i[(size_t)NMAX * KP];
__device__ __nv_bfloat16 g_wh[3][(size_t)HN * 256 * KP];
__device__ __nv_bfloat16 g_wl[3][(size_t)HN * 256 * KP];
__device__ __nv_bfloat16 g_sh[(size_t)HN * NMAX * 256];   // q/k space split
__device__ __nv_bfloat16 g_sl[(size_t)HN * NMAX * 256];
__device__ __nv_bfloat16 g_pjh[64 * 256];                  // projT split [m][k]
__device__ __nv_bfloat16 g_pjl[64 * 256];
// phi split slots: 0=uq, 1=iq, 2=ik, 3=uk
__device__ __nv_bfloat16 g_phbh[4][(size_t)HN * NMAX * MRF];
__device__ __nv_bfloat16 g_phbl[4][(size_t)HN * NMAX * MRF];
// val split slots: 0=val_u, 1=val_i   ([n][288])
__device__ __nv_bfloat16 g_vsh[2][(size_t)HN * NMAX * VSW];
__device__ __nv_bfloat16 g_vsl[2][(size_t)HN * NMAX * VSW];
// lastT split [d(288)][m]
__device__ __nv_bfloat16 g_lth[2][(size_t)HN * ZND * MRF];
__device__ __nv_bfloat16 g_ltl[2][(size_t)HN * ZND * MRF];

__device__ __forceinline__ float* bufp(int s) {
    switch (s) {
        case 0: return g_val_u;  case 1: return g_val_i;
        case 2: return g_tmp;    case 3: return g_z_i;
        case 8: return g_last_u; default: return g_last_i;
    }
}
__device__ __forceinline__ __nv_bfloat16* xhp(int s) { return s ? g_xh_i : g_xh_u; }
__device__ __forceinline__ __nv_bfloat16* xlp(int s) { return s ? g_xl_i : g_xl_u; }

__device__ __forceinline__ float wsum(float v) {
#pragma unroll
    for (int m = 16; m >= 1; m >>= 1) v += __shfl_xor_sync(0xffffffffu, v, m);
    return v;
}
__device__ __forceinline__ uint32_t smem_u32(const void* p) {
    uint32_t a;
    asm("{ .reg .u64 t; cvta.to.shared.u64 t, %1; cvt.u32.u64 %0, t; }" : "=r"(a) : "l"(p));
    return a;
}
__device__ __forceinline__ void cp16(uint32_t sa, const void* g) {
    asm volatile("cp.async.cg.shared.global [%0], [%1], 16;" :: "r"(sa), "l"(g));
}

#define LDSM_X4(r, addr)                                                           \
    asm volatile("ldmatrix.sync.aligned.m8n8.x4.shared.b16 {%0,%1,%2,%3}, [%4];"   \
        : "=r"((r)[0]), "=r"((r)[1]), "=r"((r)[2]), "=r"((r)[3]) : "r"(addr))
#define LDSM_X2(r, addr)                                                           \
    asm volatile("ldmatrix.sync.aligned.m8n8.x2.shared.b16 {%0,%1}, [%2];"         \
        : "=r"((r)[0]), "=r"((r)[1]) : "r"(addr))
#define LDSM_X4T(r, addr)                                                          \
    asm volatile("ldmatrix.sync.aligned.m8n8.x4.trans.shared.b16 {%0,%1,%2,%3}, [%4];" \
        : "=r"((r)[0]), "=r"((r)[1]), "=r"((r)[2]), "=r"((r)[3]) : "r"(addr))
#define LDSM_X2T(r, addr)                                                          \
    asm volatile("ldmatrix.sync.aligned.m8n8.x2.trans.shared.b16 {%0,%1}, [%2];"   \
        : "=r"((r)[0]), "=r"((r)[1]) : "r"(addr))
#define MMA16816(d, a, b)                                                          \
    asm volatile("mma.sync.aligned.m16n8k16.row.col.f32.bf16.bf16.f32 "            \
        "{%0,%1,%2,%3},{%4,%5,%6,%7},{%8,%9},{%0,%1,%2,%3};"                       \
        : "+f"((d)[0]), "+f"((d)[1]), "+f"((d)[2]), "+f"((d)[3])                   \
        : "r"((a)[0]), "r"((a)[1]), "r"((a)[2]), "r"((a)[3]),                      \
          "r"((b)[0]), "r"((b)[1]))

// ---- hyp smem layout ----
#define STG_BYTES 40960
#define OFF_AL 4096
#define OFF_BH 8192
#define OFF_BL 24576
#define SM_BIAS_OFF (2 * STG_BYTES)
#define SM_SS_OFF   (SM_BIAS_OFF + 1024)
#define SM_HYP_TOTAL (SM_SS_OFF + 256)

// ---- phi smem layout ----
#define PH_STG 24576
#define PH_AL 8192
#define PH_BH 16384
#define PH_BL 20480
#define PH_TOTAL (2 * PH_STG)

// ---- z smem layout ----
#define Z_AH 0
#define Z_AL 16384
#define Z_BH 32768
#define Z_BL 69632
#define Z_TOTAL 106496

// ---- last_mma smem layout: padded strides, conflict-free .trans walks ----
#define LA_STRIDE 144
#define LB_STRIDE 592
#define LM_ASTG (32 * LA_STRIDE)               // 4608
#define LM_BSTG (32 * LB_STRIDE)               // 18944
#define LM_STG  (2 * LM_ASTG + 2 * LM_BSTG)    // 47104: Ah 0 | Al | Bh | Bl
#define LM_TOTAL (2 * LM_STG)                  // 94208
#define LM_NSPLIT 70

// ---------------- converts ----------------
__global__ void convert_x_kernel(const float* __restrict__ x, int xsel, int N) {
    __nv_bfloat16* xh = xhp(xsel);
    __nv_bfloat16* xl = xlp(xsel);
    int idx = blockIdx.x * blockDim.x + threadIdx.x;
    if (idx >= N * KP) return;
    int n = idx / KP, k = idx - n * KP;
    float v = (k < DIN) ? x[(size_t)n * DIN + k] : 0.f;
    __nv_bfloat16 h = __float2bfloat16(v);
    __nv_bfloat16 l = __float2bfloat16(v - __bfloat162float(h));
    xh[idx] = h; xl[idx] = l;
}

__global__ void convert_w_kernel(const float* __restrict__ W, int m) {
    __nv_bfloat16* wh = g_wh[m];
    __nv_bfloat16* wl = g_wl[m];
    int idx = blockIdx.x * blockDim.x + threadIdx.x;
    if (idx >= HN * 256 * KP) return;
    int h = idx / (256 * KP);
    int r = idx - h * 256 * KP;
    int j = r / KP, k = r - j * KP;
    float v = (k < DIN) ? W[((size_t)h * DIN + k) * DS + j] : 0.f;
    __nv_bfloat16 hi = __float2bfloat16(v);
    __nv_bfloat16 lo = __float2bfloat16(v - __bfloat162float(hi));
    wh[idx] = hi; wl[idx] = lo;
}

__global__ void convert_proj_kernel(const float* __restrict__ proj) {
    int idx = blockIdx.x * blockDim.x + threadIdx.x;
    if (idx >= 64 * 256) return;
    int m = idx >> 8, k = idx & 255;
    float v = proj[(size_t)k * MRF + m];
    __nv_bfloat16 hi = __float2bfloat16(v);
    g_pjh[idx] = hi;
    g_pjl[idx] = __float2bfloat16(v - __bfloat162float(hi));
}

__global__ void zero_last_kernel() {
    int idx = blockIdx.x * blockDim.x + threadIdx.x;
    if (idx < HN * MRF * DIN) { g_last_u[idx] = 0.f; g_last_i[idx] = 0.f; }
}

// fp32 last [h][m][d] -> bf16 split lastT [h][d(288 pad)][m]
__global__ void last_split_kernel(int insel, int slot) {
    const float* lb = bufp(insel);
    int idx = blockIdx.x * blockDim.x + threadIdx.x;
    if (idx >= HN * ZND * MRF) return;
    int h = idx / (ZND * MRF);
    int r = idx - h * ZND * MRF;
    int d = r / MRF, m = r - d * MRF;
    float v = (d < DIN) ? lb[((size_t)h * MRF + m) * DIN + d] : 0.f;
    __nv_bfloat16 hi = __float2bfloat16(v);
    g_lth[slot][idx] = hi;
    g_ltl[slot][idx] = __float2bfloat16(v - __bfloat162float(hi));
}

// ---------------- hyp_linear via mma.sync (split-bf16 3-term) ----------------
// mode 0: fp32 out + bf16 val-split (vslot = out_sel). mode 1: q/k split + time.
__global__ __launch_bounds__(256, 2)
void hyp_mma_kernel(int xsel, int wmat, const float* __restrict__ bias,
                    int mode, int out_sel, int N)
{
    extern __shared__ char smem[];
    const int tid = threadIdx.x, wid = tid >> 5, lane = tid & 31;
    const int h = blockIdx.y, r0 = blockIdx.x * 64;
    float* out = bufp(out_sel);
    __nv_bfloat16* vsh = g_vsh[out_sel & 1];
    __nv_bfloat16* vsl = g_vsl[out_sel & 1];
    const __nv_bfloat16* xh = xhp(xsel);
    const __nv_bfloat16* xl = xlp(xsel);
    const __nv_bfloat16* wh = g_wh[wmat] + (size_t)h * 256 * KP;
    const __nv_bfloat16* wl = g_wl[wmat] + (size_t)h * 256 * KP;

    const uint32_t sb = smem_u32(smem);
    float* bias_s = (float*)(smem + SM_BIAS_OFF);
    float* ssbuf  = (float*)(smem + SM_SS_OFF);
    if (tid < 64) ssbuf[tid] = 0.f;
    bias_s[tid] = bias[h * DS + tid];

    auto load_stage = [&](int s) {
        const int k0 = s * 32;
        const uint32_t base = sb + (s & 1) * STG_BYTES;
        {
            int row = tid >> 2, c = tid & 3;
            int n = min(r0 + row, N - 1);
            uint32_t dst = base + row * 64 + ((c ^ (row & 3)) << 4);
            cp16(dst,          xh + (size_t)n * KP + k0 + c * 8);
            cp16(dst + OFF_AL, xl + (size_t)n * KP + k0 + c * 8);
        }
#pragma unroll
        for (int i = 0; i < 4; i++) {
            int u = tid + i * 256;
            int row = u >> 2, c = u & 3;
            uint32_t dst = base + OFF_BH + row * 64 + ((c ^ (row & 3)) << 4);
            cp16(dst,                   wh + (size_t)row * KP + k0 + c * 8);
            cp16(dst + (OFF_BL-OFF_BH), wl + (size_t)row * KP + k0 + c * 8);
        }
        asm volatile("cp.async.commit_group;" ::: "memory");
    };

    float acc[16][4];
#pragma unroll
    for (int i = 0; i < 16; i++)
#pragma unroll
        for (int j = 0; j < 4; j++) acc[i][j] = 0.f;

    const int wm = wid >> 2, wn = wid & 3;

    load_stage(0);
    load_stage(1);

    for (int s = 0; s < NSTG; s++) {
        if (s + 1 < NSTG) asm volatile("cp.async.wait_group 1;" ::: "memory");
        else              asm volatile("cp.async.wait_group 0;" ::: "memory");
        __syncthreads();
        const uint32_t base = sb + (s & 1) * STG_BYTES;
#pragma unroll
        for (int kh = 0; kh < 2; kh++) {
            uint32_t ah[2][4], al[2][4];
#pragma unroll
            for (int mt = 0; mt < 2; mt++) {
                int r = wm * 32 + mt * 16 + (lane & 15);
                int ch = kh * 2 + ((lane >> 4) & 1);
                uint32_t ad = base + r * 64 + ((ch ^ (r & 3)) << 4);
                LDSM_X4(ah[mt], ad);
                LDSM_X4(al[mt], ad + OFF_AL);
            }
#pragma unroll
            for (int bt = 0; bt < 8; bt++) {
                int rr = wn * 64 + bt * 8 + (lane & 7);
                int ch = kh * 2 + ((lane >> 3) & 1);
                uint32_t bd = base + OFF_BH + rr * 64 + ((ch ^ (rr & 3)) << 4);
                uint32_t bh_[2], bl_[2];
                LDSM_X2(bh_, bd);
                LDSM_X2(bl_, bd + (OFF_BL - OFF_BH));
#pragma unroll
                for (int mt = 0; mt < 2; mt++) {
                    MMA16816(acc[mt*8+bt], ah[mt], bh_);
                    MMA16816(acc[mt*8+bt], ah[mt], bl_);
                    MMA16816(acc[mt*8+bt], al[mt], bh_);
                }
            }
        }
        __syncthreads();
        if (s + 2 < NSTG) load_stage(s + 2);
    }

    // ---- epilogue ----
#pragma unroll
    for (int mt = 0; mt < 2; mt++) {
        float sslo = 0.f, sshi = 0.f;
        int rL = wm * 32 + mt * 16 + (lane >> 2);
        int n0 = r0 + rL, n1 = n0 + 8;
#pragma unroll
        for (int bt = 0; bt < 8; bt++) {
            float* d = acc[mt*8+bt];
            int cL = wn * 64 + bt * 8 + (lane & 3) * 2;
            float b0 = bias_s[cL], b1 = bias_s[cL + 1];
            float v0 = d[0] + b0, v1 = d[1] + b1;
            float v2 = d[2] + b0, v3 = d[3] + b1;
            sslo += v0 * v0 + v1 * v1;
            sshi += v2 * v2 + v3 * v3;
            if (mode == 0) {
                if (n0 < N) {
                    *(float2*)(out + ((size_t)h * N + n0) * DST + cL) = make_float2(v0, v1);
                    __nv_bfloat16 h0 = __float2bfloat16(v0), h1 = __float2bfloat16(v1);
                    *(__nv_bfloat162*)(vsh + ((size_t)h * N + n0) * VSW + cL) = __nv_bfloat162{h0, h1};
                    *(__nv_bfloat162*)(vsl + ((size_t)h * N + n0) * VSW + cL) =
                        __nv_bfloat162{__float2bfloat16(v0 - __bfloat162float(h0)),
                                       __float2bfloat16(v1 - __bfloat162float(h1))};
                }
                if (n1 < N) {
                    *(float2*)(out + ((size_t)h * N + n1) * DST + cL) = make_float2(v2, v3);
                    __nv_bfloat16 h2 = __float2bfloat16(v2), h3 = __float2bfloat16(v3);
                    *(__nv_bfloat162*)(vsh + ((size_t)h * N + n1) * VSW + cL) = __nv_bfloat162{h2, h3};
                    *(__nv_bfloat162*)(vsl + ((size_t)h * N + n1) * VSW + cL) =
                        __nv_bfloat162{__float2bfloat16(v2 - __bfloat162float(h2)),
                                       __float2bfloat16(v3 - __bfloat162float(h3))};
                }
            } else {
                if (n0 < N) {
                    __nv_bfloat16 h0 = __float2bfloat16(v0), h1 = __float2bfloat16(v1);
                    *(__nv_bfloat162*)(g_sh + ((size_t)h * N + n0) * 256 + cL) = __nv_bfloat162{h0, h1};
                    *(__nv_bfloat162*)(g_sl + ((size_t)h * N + n0) * 256 + cL) =
                        __nv_bfloat162{__float2bfloat16(v0 - __bfloat162float(h0)),
                                       __float2bfloat16(v1 - __bfloat162float(h1))};
                }
                if (n1 < N) {
                    __nv_bfloat16 h2 = __float2bfloat16(v2), h3 = __float2bfloat16(v3);
                    *(__nv_bfloat162*)(g_sh + ((size_t)h * N + n1) * 256 + cL) = __nv_bfloat162{h2, h3};
                    *(__nv_bfloat162*)(g_sl + ((size_t)h * N + n1) * 256 + cL) =
                        __nv_bfloat162{__float2bfloat16(v2 - __bfloat162float(h2)),
                                       __float2bfloat16(v3 - __bfloat162float(h3))};
                }
            }
        }
        atomicAdd(&ssbuf[rL], sslo);
        atomicAdd(&ssbuf[rL + 8], sshi);
    }
    __syncthreads();
    if (tid < 64) {
        int n = r0 + tid;
        if (n < N) {
            float t = sqrtf(1.f + ssbuf[tid]);
            if (mode == 0) {
                out[((size_t)h * N + n) * DST + DS] = t;
                size_t b = ((size_t)h * N + n) * VSW;
                __nv_bfloat16 th = __float2bfloat16(t);
                vsh[b + 256] = th;
                vsl[b + 256] = __float2bfloat16(t - __bfloat162float(th));
#pragma unroll
                for (int j = 257; j < VSW; j++) {
                    vsh[b + j] = __float2bfloat16(0.f);
                    vsl[b + j] = __float2bfloat16(0.f);
                }
            } else {
                g_time[(size_t)h * N + n] = t;
            }
        }
    }
}

// ---------------- phi via mma.sync -> bf16 split slot ----------------
__global__ __launch_bounds__(256, 2)
void phi_mma_kernel(int slot, int N)
{
    extern __shared__ char smem[];
    const int tid = threadIdx.x, wid = tid >> 5, lane = tid & 31;
    const int h = blockIdx.y, r0 = blockIdx.x * 128;
    const uint32_t sb = smem_u32(smem);

    auto load_stage = [&](int s) {
        const int k0 = s * 32;
        const uint32_t base = sb + (s & 1) * PH_STG;
#pragma unroll
        for (int i = 0; i < 2; i++) {
            int u = tid + i * 256;
            int row = u >> 2, c = u & 3;
            int n = min(r0 + row, N - 1);
            uint32_t dst = base + row * 64 + ((c ^ (row & 3)) << 4);
            cp16(dst,         g_sh + ((size_t)h * N + n) * 256 + k0 + c * 8);
            cp16(dst + PH_AL, g_sl + ((size_t)h * N + n) * 256 + k0 + c * 8);
        }
        {
            int row = tid >> 2, c = tid & 3;
            uint32_t dst = base + PH_BH + row * 64 + ((c ^ (row & 3)) << 4);
            cp16(dst,                 g_pjh + (size_t)row * 256 + k0 + c * 8);
            cp16(dst + (PH_BL-PH_BH), g_pjl + (size_t)row * 256 + k0 + c * 8);
        }
        asm volatile("cp.async.commit_group;" ::: "memory");
    };

    float acc[8][4];
#pragma unroll
    for (int i = 0; i < 8; i++)
#pragma unroll
        for (int j = 0; j < 4; j++) acc[i][j] = 0.f;

    const int wm = wid >> 1, wn = wid & 1;

    load_stage(0);
    load_stage(1);

    for (int s = 0; s < 8; s++) {
        if (s + 1 < 8) asm volatile("cp.async.wait_group 1;" ::: "memory");
        else           asm volatile("cp.async.wait_group 0;" ::: "memory");
        __syncthreads();
        const uint32_t base = sb + (s & 1) * PH_STG;
#pragma unroll
        for (int kh = 0; kh < 2; kh++) {
            uint32_t ah[2][4], al[2][4];
#pragma unroll
            for (int mt = 0; mt < 2; mt++) {
                int r = wm * 32 + mt * 16 + (lane & 15);
                int ch = kh * 2 + ((lane >> 4) & 1);
                uint32_t ad = base + r * 64 + ((ch ^ (r & 3)) << 4);
                LDSM_X4(ah[mt], ad);
                LDSM_X4(al[mt], ad + PH_AL);
            }
#pragma unroll
            for (int bt = 0; bt < 4; bt++) {
                int rr = wn * 32 + bt * 8 + (lane & 7);
                int ch = kh * 2 + ((lane >> 3) & 1);
                uint32_t bd = base + PH_BH + rr * 64 + ((ch ^ (rr & 3)) << 4);
                uint32_t bh_[2], bl_[2];
                LDSM_X2(bh_, bd);
                LDSM_X2(bl_, bd + (PH_BL - PH_BH));
#pragma unroll
                for (int mt = 0; mt < 2; mt++) {
                    MMA16816(acc[mt*4+bt], ah[mt], bh_);
                    MMA16816(acc[mt*4+bt], ah[mt], bl_);
                    MMA16816(acc[mt*4+bt], al[mt], bh_);
                }
            }
        }
        __syncthreads();
        if (s + 2 < 8) load_stage(s + 2);
    }

    const float SQT = 1.41421356237309515f;
    __nv_bfloat16* obh = g_phbh[slot];
    __nv_bfloat16* obl = g_phbl[slot];
#pragma unroll
    for (int mt = 0; mt < 2; mt++) {
        int n0 = r0 + wm * 32 + mt * 16 + (lane >> 2), n1 = n0 + 8;
        float fr0 = 0.f, fr1 = 0.f;
        if (n0 < N) { float t = g_time[(size_t)h * N + n0]; fr0 = __expf(1.f - t*t) * 0.0625f + 1e-8f; }
        if (n1 < N) { float t = g_time[(size_t)h * N + n1]; fr1 = __expf(1.f - t*t) * 0.0625f + 1e-8f; }
#pragma unroll
        for (int bt = 0; bt < 4; bt++) {
            float* d = acc[mt*4+bt];
            int cL = wn * 32 + bt * 8 + (lane & 3) * 2;
            float o0 = __expf(d[0] * SQT) * fr0;
            float o1 = __expf(d[1] * SQT) * fr0;
            float o2 = __expf(d[2] * SQT) * fr1;
            float o3 = __expf(d[3] * SQT) * fr1;
            if (n0 < N) {
                __nv_bfloat16 h0 = __float2bfloat16(o0), h1 = __float2bfloat16(o1);
                *(__nv_bfloat162*)(obh + ((size_t)h * N + n0) * MRF + cL) = __nv_bfloat162{h0, h1};
                *(__nv_bfloat162*)(obl + ((size_t)h * N + n0) * MRF + cL) =
                    __nv_bfloat162{__float2bfloat16(o0 - __bfloat162float(h0)),
                                   __float2bfloat16(o1 - __bfloat162float(h1))};
            }
            if (n1 < N) {
                __nv_bfloat16 h2 = __float2bfloat16(o2), h3 = __float2bfloat16(o3);
                *(__nv_bfloat162*)(obh + ((size_t)h * N + n1) * MRF + cL) = __nv_bfloat162{h2, h3};
                *(__nv_bfloat162*)(obl + ((size_t)h * N + n1) * MRF + cL) =
                    __nv_bfloat162{__float2bfloat16(o2 - __bfloat162float(h2)),
                                   __float2bfloat16(o3 - __bfloat162float(h3))};
            }
        }
    }
}

// ---------------- last via mma.sync (TN, ldmatrix.trans, split-K atomics) ------
// last[h,m,d] = sum_n phi[h,n,m] * val[h,n,d];  A,B both n(K)-major in memory.
__global__ __launch_bounds__(256, 2)
void last_mma_kernel(int pslot, int vslot, int out_sel, int N, int cps)
{
    extern __shared__ char smem[];
    const int tid = threadIdx.x, wid = tid >> 5, lane = tid & 31;
    const int h = blockIdx.y;
    const int Nc = N >> 5;                    // 32-row chunks (N % 32 == 0)
    const int c0 = blockIdx.z * cps;
    const int cEnd = min(c0 + cps, Nc);
    const int nch = cEnd - c0;
    if (nch <= 0) return;

    const uint32_t sb = smem_u32(smem);
    float* lb = bufp(out_sel);
    const __nv_bfloat16* ph_h = g_phbh[pslot];
    const __nv_bfloat16* ph_l = g_phbl[pslot];
    const __nv_bfloat16* vs_h = g_vsh[vslot];
    const __nv_bfloat16* vs_l = g_vsl[vslot];

    auto load_chunk = [&](int c, int buf) {
        const uint32_t base = sb + buf * LM_STG;
        const int n0 = c * 32;
        {   // A (phi): 32 rows x 8 chunks
            int row = tid >> 3, cc = tid & 7;
            size_t off = ((size_t)h * N + n0 + row) * MRF + cc * 8;
            uint32_t dst = base + row * LA_STRIDE + cc * 16;
            cp16(dst,           ph_h + off);
            cp16(dst + LM_ASTG, ph_l + off);
        }
#pragma unroll
        for (int i = 0; i < 5; i++) {   // B (val): 32 rows x 36 chunks = 1152
            int u = tid + i * 256;
            if (u < 1152) {
                int row = u / 36, cc = u - row * 36;
                size_t off = ((size_t)h * N + n0 + row) * VSW + cc * 8;
                uint32_t dst = base + 2 * LM_ASTG + row * LB_STRIDE + cc * 16;
                cp16(dst,           vs_h + off);
                cp16(dst + LM_BSTG, vs_l + off);
            }
        }
        asm volatile("cp.async.commit_group;" ::: "memory");
    };

    float acc[18][4];
#pragma unroll
    for (int i = 0; i < 18; i++)
#pragma unroll
        for (int j = 0; j < 4; j++) acc[i][j] = 0.f;

    const int wm = wid >> 2, wn = wid & 3;   // m: wm*32 (2 mt), d: wn*72 (9 bt)

    load_chunk(c0, 0);
    if (nch > 1) load_chunk(c0 + 1, 1);

    for (int s = 0; s < nch; s++) {
        if (s + 1 < nch) asm volatile("cp.async.wait_group 1;" ::: "memory");
        else             asm volatile("cp.async.wait_group 0;" ::: "memory");
        __syncthreads();
        const uint32_t base = sb + (s & 1) * LM_STG;
        const uint32_t bbase = base + 2 * LM_ASTG;
#pragma unroll
        for (int kh = 0; kh < 2; kh++) {
            // A fragments (.trans): row = k-index, coloff = m
            uint32_t ah[2][4], al[2][4];
            {
                int rowA = kh * 16 + (lane & 7) + ((lane >> 4) & 1) * 8;
#pragma unroll
                for (int mt = 0; mt < 2; mt++) {
                    int m0 = wm * 32 + mt * 16;
                    uint32_t ad = base + rowA * LA_STRIDE + m0 * 2 + ((lane >> 3) & 1) * 16;
                    LDSM_X4T(ah[mt], ad);
                    LDSM_X4T(al[mt], ad + LM_ASTG);
                }
            }
            int rowB = kh * 16 + (lane & 7) + ((lane >> 3) & 1) * 8;
#pragma unroll
            for (int bp = 0; bp < 4; bp++) {    // bt pairs (0,1)..(6,7)
                int d0 = wn * 72 + bp * 16;
                uint32_t bd = bbase + rowB * LB_STRIDE + d0 * 2 + ((lane >> 4) & 1) * 16;
                uint32_t bh4[4], bl4[4];
                LDSM_X4T(bh4, bd);
                LDSM_X4T(bl4, bd + LM_BSTG);
#pragma unroll
                for (int half = 0; half < 2; half++) {
                    uint32_t* bh_ = bh4 + half * 2;
                    uint32_t* bl_ = bl4 + half * 2;
                    int bt = bp * 2 + half;
#pragma unroll
                    for (int mt = 0; mt < 2; mt++) {
                        MMA16816(acc[mt*9+bt], ah[mt], bh_);
                        MMA16816(acc[mt*9+bt], ah[mt], bl_);
                        MMA16816(acc[mt*9+bt], al[mt], bh_);
                    }
                }
            }
            {   // bt = 8 single
                int d0 = wn * 72 + 64;
                uint32_t bd = bbase + rowB * LB_STRIDE + d0 * 2;
                uint32_t bh_[2], bl_[2];
                LDSM_X2T(bh_, bd);
                LDSM_X2T(bl_, bd + LM_BSTG);
#pragma unroll
                for (int mt = 0; mt < 2; mt++) {
                    MMA16816(acc[mt*9+8], ah[mt], bh_);
                    MMA16816(acc[mt*9+8], ah[mt], bl_);
                    MMA16816(acc[mt*9+8], al[mt], bh_);
                }
            }
        }
        __syncthreads();
        if (s + 2 < nch) load_chunk(c0 + s + 2, s & 1);
    }

    // ---- epilogue: fp32 atomics into last[h][m][d] ----
#pragma unroll
    for (int mt = 0; mt < 2; mt++) {
        int m0r = wm * 32 + mt * 16 + (lane >> 2);
#pragma unroll
        for (int bt = 0; bt < 9; bt++) {
            float* d = acc[mt*9+bt];
            int dc = wn * 72 + bt * 8 + (lane & 3) * 2;
            size_t b0 = ((size_t)h * MRF + m0r) * DIN;
            size_t b1 = ((size_t)h * MRF + m0r + 8) * DIN;
            if (dc < DIN)     { atomicAdd(&lb[b0 + dc],     d[0]); atomicAdd(&lb[b1 + dc],     d[2]); }
            if (dc + 1 < DIN) { atomicAdd(&lb[b0 + dc + 1], d[1]); atomicAdd(&lb[b1 + dc + 1], d[3]); }
        }
    }
}

// ---------------- z via mma.sync ----------------
__global__ __launch_bounds__(256)
void z_mma_kernel(int slot, int out_sel, int N)
{
    extern __shared__ char smem[];
    const int tid = threadIdx.x, wid = tid >> 5, lane = tid & 31;
    const int h = blockIdx.y, r0 = blockIdx.x * 128;
    const uint32_t sb = smem_u32(smem);
    float* zb = bufp(out_sel);
    const __nv_bfloat16* ah_g = g_phbh[slot];
    const __nv_bfloat16* al_g = g_phbl[slot];
    const __nv_bfloat16* bh_g = g_lth[slot];
    const __nv_bfloat16* bl_g = g_ltl[slot];

#pragma unroll
    for (int i = 0; i < 4; i++) {
        int u = tid + i * 256;
        int row = u >> 3, c = u & 7;
        int n = min(r0 + row, N - 1);
        uint32_t dst = sb + Z_AH + row * 128 + ((c ^ (row & 7)) << 4);
        cp16(dst,               ah_g + ((size_t)h * N + n) * MRF + c * 8);
        cp16(dst + (Z_AL-Z_AH), al_g + ((size_t)h * N + n) * MRF + c * 8);
    }
#pragma unroll
    for (int i = 0; i < 9; i++) {
        int u = tid + i * 256;
        int row = u >> 3, c = u & 7;
        uint32_t dst = sb + Z_BH + row * 128 + ((c ^ (row & 7)) << 4);
        cp16(dst,               bh_g + ((size_t)h * ZND + row) * MRF + c * 8);
        cp16(dst + (Z_BL-Z_BH), bl_g + ((size_t)h * ZND + row) * MRF + c * 8);
    }
    asm volatile("cp.async.commit_group;" ::: "memory");
    asm volatile("cp.async.wait_group 0;" ::: "memory");
    __syncthreads();

    float acc[36][4];
#pragma unroll
    for (int i = 0; i < 36; i++)
#pragma unroll
        for (int j = 0; j < 4; j++) acc[i][j] = 0.f;

    const int wm = wid >> 2, wn = wid & 3;

#pragma unroll
    for (int kh = 0; kh < 4; kh++) {
        uint32_t ah[4][4], al[4][4];
#pragma unroll
        for (int mt = 0; mt < 4; mt++) {
            int r = wm * 64 + mt * 16 + (lane & 15);
            int ch = kh * 2 + ((lane >> 4) & 1);
            uint32_t ad = sb + Z_AH + r * 128 + ((ch ^ (r & 7)) << 4);
            LDSM_X4(ah[mt], ad);
            LDSM_X4(al[mt], ad + (Z_AL - Z_AH));
        }
#pragma unroll
        for (int bt = 0; bt < 9; bt++) {
            int rr = wn * 72 + bt * 8 + (lane & 7);
            int ch = kh * 2 + ((lane >> 3) & 1);
            uint32_t bd = sb + Z_BH + rr * 128 + ((ch ^ (rr & 7)) << 4);
            uint32_t bh_[2], bl_[2];
            LDSM_X2(bh_, bd);
            LDSM_X2(bl_, bd + (Z_BL - Z_BH));
#pragma unroll
            for (int mt = 0; mt < 4; mt++) {
                MMA16816(acc[mt*9+bt], ah[mt], bh_);
                MMA16816(acc[mt*9+bt], ah[mt], bl_);
                MMA16816(acc[mt*9+bt], al[mt], bh_);
            }
        }
    }

#pragma unroll
    for (int mt = 0; mt < 4; mt++) {
        int n0 = r0 + wm * 64 + mt * 16 + (lane >> 2), n1 = n0 + 8;
#pragma unroll
        for (int bt = 0; bt < 9; bt++) {
            float* d = acc[mt*9+bt];
            int cL = wn * 72 + bt * 8 + (lane & 3) * 2;
            if (cL < 256) {
                if (n0 < N) *(float2*)(zb + ((size_t)h * N + n0) * DST + cL) = make_float2(d[0], d[1]);
                if (n1 < N) *(float2*)(zb + ((size_t)h * N + n1) * DST + cL) = make_float2(d[2], d[3]);
            } else if (cL == 256) {
                if (n0 < N) zb[((size_t)h * N + n0) * DST + 256] = d[0];
                if (n1 < N) zb[((size_t)h * N + n1) * DST + 256] = d[2];
            }
        }
    }
}

// ---------------- finalize ----------------
__global__ __launch_bounds__(256) void final_kernel(int val_sel, int z_sel,
                                                    float* __restrict__ out, int N)
{
    const float* val = bufp(val_sel);
    const float* zb  = bufp(z_sel);
    const int warp = threadIdx.x >> 5;
    const int lane = threadIdx.x & 31;
    const int n = blockIdx.x * 8 + warp;
    if (n >= N) return;

    float mean[9];
#pragma unroll
    for (int jj = 0; jj < 9; jj++) mean[jj] = 0.f;

    for (int h = 0; h < HN; h++) {
        const float* zr = zb  + ((size_t)h * N + n) * DST;
        const float* ar = val + ((size_t)h * N + n) * DST;
        float zv[9], av[9];
        float mq = 0.f;
#pragma unroll
        for (int jj = 0; jj < 9; jj++) {
            int d = lane + jj * 32;
            bool ok = d < DIN;
            float zz = ok ? zr[d] : 0.f;
            float aa = ok ? ar[d] : 0.f;
            zv[jj] = zz; av[jj] = aa;
            mq += zz * zz * ((d == DS) ? -1.f : 1.f);
        }
        mq = wsum(mq);
        float coeff = rsqrtf(fabsf(mq + 1e-7f));
        float ab = 0.f, a2 = 0.f, b2 = 0.f;
#pragma unroll
        for (int jj = 0; jj < 9; jj++) {
            float b = zv[jj] * coeff;
            zv[jj] = b;
            ab += av[jj] * b;
            a2 += av[jj] * av[jj];
            b2 += b * b;
        }
        ab = wsum(ab); a2 = wsum(a2); b2 = wsum(b2);
        float t1  = 1.f + 2.f * ab + b2;
        float t2  = 1.f - a2;
        float inv = 1.f / (1.f + 2.f * ab + a2 * b2 + 1e-7f);
#pragma unroll
        for (int jj = 0; jj < 9; jj++)
            mean[jj] += 0.25f * (t1 * av[jj] + t2 * zv[jj]) * inv;
    }

    float mq = 0.f;
#pragma unroll
    for (int jj = 0; jj < 9; jj++) {
        int d = lane + jj * 32;
        if (d < DIN) mq += mean[jj] * mean[jj] * ((d == DS) ? -1.f : 1.f);
    }
    mq = wsum(mq);
    float cf = rsqrtf(fabsf(mq) + 1e-7f);
#pragma unroll
    for (int jj = 0; jj < 9; jj++) {
        int d = lane + jj * 32;
        if (d < DIN) {
            int pos = (d == DS) ? 0 : (d + 1);
            out[(size_t)n * DIN + pos] = mean[jj] * cf;
        }
    }
}

// ---------------- launch ----------------
extern "C" void kernel_launch(void* const* d_in, const int* in_sizes, int n_in,
                              void* d_out, int out_size)
{
    const float* u    = (const float*)d_in[0];
    const float* iT   = (const float*)d_in[1];
    const float* Wk   = (const float*)d_in[2];
    const float* bk   = (const float*)d_in[3];
    const float* Wq   = (const float*)d_in[4];
    const float* bq   = (const float*)d_in[5];
    const float* Wv   = (const float*)d_in[6];
    const float* bv   = (const float*)d_in[7];
    const float* proj = (const float*)d_in[8];
    float* out = (float*)d_out;
    const int N = in_sizes[0] / DIN;   // 20000

    cudaFuncSetAttribute(hyp_mma_kernel,  cudaFuncAttributeMaxDynamicSharedMemorySize, SM_HYP_TOTAL);
    cudaFuncSetAttribute(phi_mma_kernel,  cudaFuncAttributeMaxDynamicSharedMemorySize, PH_TOTAL);
    cudaFuncSetAttribute(z_mma_kernel,    cudaFuncAttributeMaxDynamicSharedMemorySize, Z_TOTAL);
    cudaFuncSetAttribute(last_mma_kernel, cudaFuncAttributeMaxDynamicSharedMemorySize, LM_TOTAL);

    dim3 bh(256);
    dim3 gm((N + 63) / 64, HN);
    dim3 gp((N + 127) / 128, HN);
    const int Nc = N / 32;
    const int cps = (Nc + LM_NSPLIT - 1) / LM_NSPLIT;
    dim3 glm(1, HN, LM_NSPLIT);

    // converts
    int cx = (N * KP + 255) / 256;
    convert_x_kernel<<<cx, 256>>>(u,  0, N);
    convert_x_kernel<<<cx, 256>>>(iT, 1, N);
    int cw = (HN * 256 * KP + 255) / 256;
    convert_w_kernel<<<cw, 256>>>(Wk, 0);
    convert_w_kernel<<<cw, 256>>>(Wq, 1);
    convert_w_kernel<<<cw, 256>>>(Wv, 2);
    convert_proj_kernel<<<(64 * 256 + 255) / 256, 256>>>(proj);
    zero_last_kernel<<<(HN * MRF * DIN + 255) / 256, 256>>>();

    // values (fp32 + val-split)
    hyp_mma_kernel<<<gm, bh, SM_HYP_TOTAL>>>(0, 2, bv, 0, 0, N);   // val_u (vslot 0)
    hyp_mma_kernel<<<gm, bh, SM_HYP_TOTAL>>>(1, 2, bv, 0, 1, N);   // val_i (vslot 1)

    // queries/keys + phi (slots: 0=uq, 1=iq, 2=ik, 3=uk)
    hyp_mma_kernel<<<gm, bh, SM_HYP_TOTAL>>>(0, 1, bq, 1, 0, N);   // u_query
    phi_mma_kernel<<<gp, bh, PH_TOTAL>>>(0, N);
    hyp_mma_kernel<<<gm, bh, SM_HYP_TOTAL>>>(1, 0, bk, 1, 0, N);   // i_key
    phi_mma_kernel<<<gp, bh, PH_TOTAL>>>(2, N);
    hyp_mma_kernel<<<gm, bh, SM_HYP_TOTAL>>>(1, 1, bq, 1, 0, N);   // i_query
    phi_mma_kernel<<<gp, bh, PH_TOTAL>>>(1, N);
    hyp_mma_kernel<<<gm, bh, SM_HYP_TOTAL>>>(0, 0, bk, 1, 0, N);   // u_key
    phi_mma_kernel<<<gp, bh, PH_TOTAL>>>(3, N);

    // last via MMA (split-K atomics)
    last_mma_kernel<<<glm, bh, LM_TOTAL>>>(2, 1, 8, N, cps);   // last_u = phi_ik^T @ val_i
    last_mma_kernel<<<glm, bh, LM_TOTAL>>>(3, 0, 9, N, cps);   // last_i = phi_uk^T @ val_u

    // lastT bf16 splits
    int cl = (HN * ZND * MRF + 255) / 256;
    last_split_kernel<<<cl, 256>>>(8, 0);
    last_split_kernel<<<cl, 256>>>(9, 1);

    // z via MMA
    z_mma_kernel<<<gp, bh, Z_TOTAL>>>(0, 2, N);
    z_mma_kernel<<<gp, bh, Z_TOTAL>>>(1, 3, N);

    final_kernel<<<dim3((N + 7) / 8), bh>>>(0, 2, out, N);
    final_kernel<<<dim3((N + 7) / 8), bh>>>(1, 3, out + (size_t)N * DIN, N);
}